// round 5
// baseline (speedup 1.0000x reference)
#include <cuda_runtime.h>
#include <stdint.h>

#define NREP 8
#define MAXPIX 4194304
#define SCANT 512      // threads in scan blocks
#define BPT   128      // bins per scan thread (SCANT*BPT = 65536)

// ---------------- device scratch ----------------
__device__ double             g_acc[9];
__device__ unsigned long long g_cnt;
__device__ unsigned           g_hist [NREP][65536];
__device__ unsigned           g_histC0[NREP][65536];
__device__ unsigned           g_histC1[NREP][65536];
__device__ unsigned           g_hist2[8][65536];
__device__ float              g_phi[MAXPIX];
__device__ float              g_c0[MAXPIX];
__device__ float              g_c1[MAXPIX];
__device__ float              g_E[6];        // e_mid(0..2), e_lg(3..5)
__device__ float              g_A[6];        // (HE^T HE)^-1 HE^T   (2x3)
__device__ float              g_G[9];        // fused 3x3
__device__ unsigned           g_topbin[8];
__device__ unsigned           g_rankin[8];
__device__ float              g_frac[3];

// ---------------- helpers ----------------
__device__ __forceinline__ unsigned fkey(float x){
  unsigned u = __float_as_uint(x);
  return (u & 0x80000000u) ? ~u : (u | 0x80000000u);
}
__device__ __forceinline__ unsigned ukey(unsigned u){
  return (u & 0x80000000u) ? ~u : (u | 0x80000000u);
}
__device__ __forceinline__ float keyf(unsigned k){
  return __uint_as_float((k & 0x80000000u) ? (k ^ 0x80000000u) : ~k);
}
__device__ __forceinline__ float odv(float p){
  return -logf((floorf(p * 255.0f) + 1.0f) / 240.0f);
}

// ---------------- zero ----------------
__global__ void __launch_bounds__(256, 1) k_zero(){
  int j = blockIdx.x * blockDim.x + threadIdx.x;
  int stride = gridDim.x * blockDim.x;
  for (int i = j; i < 65536; i += stride){
    #pragma unroll
    for (int r = 0; r < NREP; r++){
      g_hist[r][i] = 0u; g_histC0[r][i] = 0u; g_histC1[r][i] = 0u; g_hist2[r][i] = 0u;
    }
  }
  if (j == 0){
    g_cnt = 0ull;
    for (int k = 0; k < 9; k++) g_acc[k] = 0.0;
  }
}

// ---------------- pass 1: masked stats (f64) ----------------
__global__ void __launch_bounds__(256) k_stats(const float* __restrict__ img, int npix){
  int n4 = npix >> 2;
  const float4* R  = (const float4*)img;
  const float4* Gp = R + n4;
  const float4* Bp = R + 2 * n4;
  double a[9] = {0,0,0,0,0,0,0,0,0};
  unsigned cnt = 0;
  int stride = gridDim.x * blockDim.x;
  for (int i = blockIdx.x * blockDim.x + threadIdx.x; i < n4; i += stride){
    float4 r = R[i], g = Gp[i], b = Bp[i];
    float rr[4] = {r.x, r.y, r.z, r.w};
    float gg[4] = {g.x, g.y, g.z, g.w};
    float bb[4] = {b.x, b.y, b.z, b.w};
    #pragma unroll
    for (int j = 0; j < 4; j++){
      float o0f = odv(rr[j]), o1f = odv(gg[j]), o2f = odv(bb[j]);
      if (o0f >= 0.15f && o1f >= 0.15f && o2f >= 0.15f){
        double o0 = o0f, o1 = o1f, o2 = o2f;
        a[0] += o0; a[1] += o1; a[2] += o2;
        a[3] += o0*o0; a[4] += o0*o1; a[5] += o0*o2;
        a[6] += o1*o1; a[7] += o1*o2; a[8] += o2*o2;
        cnt++;
      }
    }
  }
  double c = (double)cnt;
  #pragma unroll
  for (int o = 16; o > 0; o >>= 1){
    #pragma unroll
    for (int k = 0; k < 9; k++) a[k] += __shfl_down_sync(0xffffffffu, a[k], o);
    c += __shfl_down_sync(0xffffffffu, c, o);
  }
  __shared__ double s_acc[10][8];
  int w = threadIdx.x >> 5, lane = threadIdx.x & 31;
  if (lane == 0){
    #pragma unroll
    for (int k = 0; k < 9; k++) s_acc[k][w] = a[k];
    s_acc[9][w] = c;
  }
  __syncthreads();
  if (threadIdx.x == 0){
    int nw = blockDim.x >> 5;
    double t[10] = {0,0,0,0,0,0,0,0,0,0};
    for (int ww = 0; ww < nw; ww++)
      for (int k = 0; k < 10; k++) t[k] += s_acc[k][ww];
    for (int k = 0; k < 9; k++) atomicAdd(&g_acc[k], t[k]);
    atomicAdd(&g_cnt, (unsigned long long)(t[9] + 0.5));
  }
}

// ---------------- pass 2: 3x3 eigh (double Jacobi, 1 thread) ----------------
__global__ void __launch_bounds__(32, 1) k_eig(){
  if (threadIdx.x != 0 || blockIdx.x != 0) return;
  double n = (double)g_cnt;
  double s0 = g_acc[0], s1 = g_acc[1], s2 = g_acc[2];
  double inv = 1.0 / (n - 1.0);
  double a[3][3];
  a[0][0] = (g_acc[3] - s0*s0/n) * inv;
  a[0][1] = a[1][0] = (g_acc[4] - s0*s1/n) * inv;
  a[0][2] = a[2][0] = (g_acc[5] - s0*s2/n) * inv;
  a[1][1] = (g_acc[6] - s1*s1/n) * inv;
  a[1][2] = a[2][1] = (g_acc[7] - s1*s2/n) * inv;
  a[2][2] = (g_acc[8] - s2*s2/n) * inv;
  double V[3][3] = {{1,0,0},{0,1,0},{0,0,1}};
  for (int sweep = 0; sweep < 50; sweep++){
    double off = fabs(a[0][1]) + fabs(a[0][2]) + fabs(a[1][2]);
    if (off == 0.0) break;
    for (int p = 0; p < 2; p++){
      for (int q = p + 1; q < 3; q++){
        double apq = a[p][q];
        if (fabs(apq) < 1e-300) continue;
        double theta = (a[q][q] - a[p][p]) / (2.0 * apq);
        double t = (theta >= 0.0 ? 1.0 : -1.0) / (fabs(theta) + sqrt(theta*theta + 1.0));
        double c = 1.0 / sqrt(t*t + 1.0);
        double s = t * c;
        double app = a[p][p], aqq = a[q][q];
        a[p][p] = app - t * apq;
        a[q][q] = aqq + t * apq;
        a[p][q] = a[q][p] = 0.0;
        int r = 3 - p - q;
        double arp = a[r][p], arq = a[r][q];
        a[r][p] = a[p][r] = c*arp - s*arq;
        a[r][q] = a[q][r] = s*arp + c*arq;
        for (int k = 0; k < 3; k++){
          double vkp = V[k][p], vkq = V[k][q];
          V[k][p] = c*vkp - s*vkq;
          V[k][q] = s*vkp + c*vkq;
        }
      }
    }
  }
  double w[3] = {a[0][0], a[1][1], a[2][2]};
  int idx[3] = {0,1,2};
  for (int i = 0; i < 2; i++)
    for (int j = i + 1; j < 3; j++)
      if (w[idx[j]] < w[idx[i]]){ int tmp = idx[i]; idx[i] = idx[j]; idx[j] = tmp; }
  int cols[2] = {idx[1], idx[2]};   // middle, largest eigenvalue
  for (int j = 0; j < 2; j++){
    double v0 = V[0][cols[j]], v1 = V[1][cols[j]], v2 = V[2][cols[j]];
    double mx = v0, mxa = fabs(v0);
    if (fabs(v1) > mxa){ mxa = fabs(v1); mx = v1; }
    if (fabs(v2) > mxa){ mxa = fabs(v2); mx = v2; }
    double sgn = (mx < 0.0) ? -1.0 : 1.0;   // sign convention (flip candidate)
    g_E[3*j+0] = (float)(v0 * sgn);
    g_E[3*j+1] = (float)(v1 * sgn);
    g_E[3*j+2] = (float)(v2 * sgn);
  }
}

// ---------------- pass 3: phi + top-16 histogram ----------------
__global__ void __launch_bounds__(256) k_phi(const float* __restrict__ img, int npix){
  int n4 = npix >> 2;
  const float4* R  = (const float4*)img;
  const float4* Gp = R + n4;
  const float4* Bp = R + 2 * n4;
  float4* PH = (float4*)g_phi;
  float e0=g_E[0],e1=g_E[1],e2=g_E[2],e3=g_E[3],e4=g_E[4],e5=g_E[5];
  unsigned rep = blockIdx.x & (NREP - 1);
  int stride = gridDim.x * blockDim.x;
  for (int i = blockIdx.x * blockDim.x + threadIdx.x; i < n4; i += stride){
    float4 r = R[i], g = Gp[i], b = Bp[i];
    float rr[4] = {r.x, r.y, r.z, r.w};
    float gg[4] = {g.x, g.y, g.z, g.w};
    float bb[4] = {b.x, b.y, b.z, b.w};
    float ph[4];
    #pragma unroll
    for (int j = 0; j < 4; j++){
      float o0 = odv(rr[j]), o1 = odv(gg[j]), o2 = odv(bb[j]);
      if (o0 >= 0.15f && o1 >= 0.15f && o2 >= 0.15f){
        float t0 = o0*e0 + o1*e1 + o2*e2;
        float t1 = o0*e3 + o1*e4 + o2*e5;
        float p = atan2f(t1, t0);
        ph[j] = p;
        atomicAdd(&g_hist[rep][fkey(p) >> 16], 1u);
      } else {
        ph[j] = __int_as_float(0x7f800000);   // +inf: sorts last, never histogrammed
      }
    }
    PH[i] = make_float4(ph[0], ph[1], ph[2], ph[3]);
  }
}

// ---------------- block scan infra (blockDim == SCANT) ----------------
__device__ unsigned blk_exscan(unsigned v){
  __shared__ unsigned ws[32];
  unsigned lane = threadIdx.x & 31, w = threadIdx.x >> 5;
  unsigned x = v;
  #pragma unroll
  for (int o = 1; o < 32; o <<= 1){
    unsigned y = __shfl_up_sync(0xffffffffu, x, o);
    if (lane >= o) x += y;
  }
  if (lane == 31) ws[w] = x;
  __syncthreads();
  if (threadIdx.x < 32){
    unsigned t = (lane < (SCANT / 32)) ? ws[lane] : 0u;
    #pragma unroll
    for (int o = 1; o < 32; o <<= 1){
      unsigned y = __shfl_up_sync(0xffffffffu, t, o);
      if (lane >= o) t += y;
    }
    ws[lane] = t;
  }
  __syncthreads();
  unsigned base = (w == 0) ? 0u : ws[w - 1];
  unsigned res = base + x - v;
  __syncthreads();
  return res;
}

__device__ __forceinline__ unsigned sumrep(const unsigned (*h)[65536], unsigned bin){
  unsigned s = 0;
  #pragma unroll
  for (int r = 0; r < NREP; r++) s += h[r][bin];
  return s;
}

// find k-th over an NREP-replicated 65536-bin histogram
__device__ void find_kth(const unsigned (*hist)[65536], unsigned rank,
                         unsigned* out_bin, unsigned* out_rib){
  unsigned base = threadIdx.x * BPT;
  unsigned s = 0;
  for (int b = 0; b < BPT; b++) s += sumrep(hist, base + b);
  unsigned cum = blk_exscan(s);
  if (rank >= cum && rank < cum + s){
    for (int b = 0; b < BPT; b++){
      unsigned h = sumrep(hist, base + b);
      if (rank < cum + h){ *out_bin = base + b; *out_rib = rank - cum; break; }
      cum += h;
    }
  }
  __syncthreads();
}

// find k-th over a plain 65536-bin low-16 histogram, return reconstructed float
__device__ float find_val16(const unsigned* __restrict__ hist, unsigned rank, unsigned topbin){
  __shared__ float s_val;
  unsigned base = threadIdx.x * BPT;
  unsigned s = 0;
  for (int b = 0; b < BPT; b++) s += hist[base + b];
  unsigned cum = blk_exscan(s);
  if (rank >= cum && rank < cum + s){
    for (int b = 0; b < BPT; b++){
      unsigned h = hist[base + b];
      if (rank < cum + h){ s_val = keyf((topbin << 16) | (base + b)); break; }
      cum += h;
    }
  }
  __syncthreads();
  float v = s_val;
  __syncthreads();
  return v;
}

// ---------------- pass 4: phi quantile top bins ----------------
__global__ void __launch_bounds__(SCANT, 1) k_scan1(){
  __shared__ unsigned sh_rank[4];
  if (threadIdx.x == 0){
    unsigned n = (unsigned)g_cnt;
    float nm1 = (float)(n - 1u);
    float p0 = 0.01f * nm1, p1 = 0.99f * nm1;
    float l0 = floorf(p0), l1 = floorf(p1);
    sh_rank[0] = (unsigned)l0; sh_rank[1] = (unsigned)ceilf(p0);
    sh_rank[2] = (unsigned)l1; sh_rank[3] = (unsigned)ceilf(p1);
    g_frac[0] = p0 - l0; g_frac[1] = p1 - l1;
  }
  __syncthreads();
  for (int q = 0; q < 4; q++)
    find_kth(g_hist, sh_rank[q], &g_topbin[q], &g_rankin[q]);
}

// ---------------- pass 5: phi refine ----------------
__global__ void __launch_bounds__(256) k_refine1(int npix){
  const uint4* P = (const uint4*)g_phi;
  unsigned tb0 = g_topbin[0], tb1 = g_topbin[1], tb2 = g_topbin[2], tb3 = g_topbin[3];
  int n4 = npix >> 2;
  int stride = gridDim.x * blockDim.x;
  for (int i = blockIdx.x * blockDim.x + threadIdx.x; i < n4; i += stride){
    uint4 u = P[i];
    unsigned kk[4] = {ukey(u.x), ukey(u.y), ukey(u.z), ukey(u.w)};
    #pragma unroll
    for (int j = 0; j < 4; j++){
      unsigned top = kk[j] >> 16, low = kk[j] & 0xffffu;
      if (top == tb0) atomicAdd(&g_hist2[0][low], 1u);
      if (top == tb1) atomicAdd(&g_hist2[1][low], 1u);
      if (top == tb2) atomicAdd(&g_hist2[2][low], 1u);
      if (top == tb3) atomicAdd(&g_hist2[3][low], 1u);
    }
  }
}

// ---------------- pass 6: HE + solve matrix ----------------
__global__ void __launch_bounds__(SCANT, 1) k_scan2(){
  float v[4];
  for (int q = 0; q < 4; q++)
    v[q] = find_val16(g_hist2[q], g_rankin[q], g_topbin[q]);
  if (threadIdx.x == 0){
    float f0 = g_frac[0], f1 = g_frac[1];
    float minPhi = v[0] * (1.0f - f0) + v[1] * f0;
    float maxPhi = v[2] * (1.0f - f1) + v[3] * f1;
    float cmn = cosf(minPhi), smn = sinf(minPhi);
    float cmx = cosf(maxPhi), smx = sinf(maxPhi);
    float vMin[3], vMax[3];
    for (int i = 0; i < 3; i++){
      vMin[i] = g_E[i] * cmn + g_E[3 + i] * smn;
      vMax[i] = g_E[i] * cmx + g_E[3 + i] * smx;
    }
    float he[3][2];
    if (vMin[0] > vMax[0])
      for (int i = 0; i < 3; i++){ he[i][0] = vMin[i]; he[i][1] = vMax[i]; }
    else
      for (int i = 0; i < 3; i++){ he[i][0] = vMax[i]; he[i][1] = vMin[i]; }
    double m00 = 0, m01 = 0, m11 = 0;
    for (int i = 0; i < 3; i++){
      m00 += (double)he[i][0] * he[i][0];
      m01 += (double)he[i][0] * he[i][1];
      m11 += (double)he[i][1] * he[i][1];
    }
    double det = m00 * m11 - m01 * m01;
    double i00 = m11 / det, i01 = -m01 / det, i11 = m00 / det;
    for (int j = 0; j < 3; j++){
      g_A[j]     = (float)(i00 * he[j][0] + i01 * he[j][1]);
      g_A[3 + j] = (float)(i01 * he[j][0] + i11 * he[j][1]);
    }
  }
}

// ---------------- pass 7: C + histograms ----------------
__global__ void __launch_bounds__(256) k_C(const float* __restrict__ img, int npix){
  int n4 = npix >> 2;
  const float4* R  = (const float4*)img;
  const float4* Gp = R + n4;
  const float4* Bp = R + 2 * n4;
  float4* C0 = (float4*)g_c0;
  float4* C1 = (float4*)g_c1;
  float a0=g_A[0],a1=g_A[1],a2=g_A[2],a3=g_A[3],a4=g_A[4],a5=g_A[5];
  unsigned rep = blockIdx.x & (NREP - 1);
  int stride = gridDim.x * blockDim.x;
  for (int i = blockIdx.x * blockDim.x + threadIdx.x; i < n4; i += stride){
    float4 r = R[i], g = Gp[i], b = Bp[i];
    float rr[4] = {r.x, r.y, r.z, r.w};
    float gg[4] = {g.x, g.y, g.z, g.w};
    float bb[4] = {b.x, b.y, b.z, b.w};
    float c0v[4], c1v[4];
    #pragma unroll
    for (int j = 0; j < 4; j++){
      float o0 = odv(rr[j]), o1 = odv(gg[j]), o2 = odv(bb[j]);
      float c0 = o0*a0 + o1*a1 + o2*a2;
      float c1 = o0*a3 + o1*a4 + o2*a5;
      c0v[j] = c0; c1v[j] = c1;
      atomicAdd(&g_histC0[rep][fkey(c0) >> 16], 1u);
      atomicAdd(&g_histC1[rep][fkey(c1) >> 16], 1u);
    }
    C0[i] = make_float4(c0v[0], c0v[1], c0v[2], c0v[3]);
    C1[i] = make_float4(c1v[0], c1v[1], c1v[2], c1v[3]);
  }
}

// ---------------- pass 8: C quantile top bins ----------------
__global__ void __launch_bounds__(SCANT, 1) k_scan3(int npix){
  __shared__ unsigned sh_rank[2];
  if (threadIdx.x == 0){
    float nm1 = (float)(npix - 1);
    float p = 0.99f * nm1;
    float l = floorf(p);
    sh_rank[0] = (unsigned)l;
    sh_rank[1] = (unsigned)ceilf(p);
    g_frac[2] = p - l;
  }
  __syncthreads();
  find_kth(g_histC0, sh_rank[0], &g_topbin[4], &g_rankin[4]);
  find_kth(g_histC0, sh_rank[1], &g_topbin[5], &g_rankin[5]);
  find_kth(g_histC1, sh_rank[0], &g_topbin[6], &g_rankin[6]);
  find_kth(g_histC1, sh_rank[1], &g_topbin[7], &g_rankin[7]);
}

// ---------------- pass 9: C refine ----------------
__global__ void __launch_bounds__(256) k_refine2(int npix){
  const uint4* P0 = (const uint4*)g_c0;
  const uint4* P1 = (const uint4*)g_c1;
  unsigned tb4 = g_topbin[4], tb5 = g_topbin[5], tb6 = g_topbin[6], tb7 = g_topbin[7];
  int n4 = npix >> 2;
  int stride = gridDim.x * blockDim.x;
  for (int i = blockIdx.x * blockDim.x + threadIdx.x; i < n4; i += stride){
    uint4 u0 = P0[i], u1 = P1[i];
    unsigned k0[4] = {ukey(u0.x), ukey(u0.y), ukey(u0.z), ukey(u0.w)};
    unsigned k1[4] = {ukey(u1.x), ukey(u1.y), ukey(u1.z), ukey(u1.w)};
    #pragma unroll
    for (int j = 0; j < 4; j++){
      unsigned t0 = k0[j] >> 16, l0 = k0[j] & 0xffffu;
      unsigned t1 = k1[j] >> 16, l1 = k1[j] & 0xffffu;
      if (t0 == tb4) atomicAdd(&g_hist2[4][l0], 1u);
      if (t0 == tb5) atomicAdd(&g_hist2[5][l0], 1u);
      if (t1 == tb6) atomicAdd(&g_hist2[6][l1], 1u);
      if (t1 == tb7) atomicAdd(&g_hist2[7][l1], 1u);
    }
  }
}

// ---------------- pass 10: fuse G ----------------
__global__ void __launch_bounds__(SCANT, 1) k_scan4(const float* __restrict__ HERef, const float* __restrict__ maxCRef){
  float v[4];
  for (int q = 0; q < 4; q++)
    v[q] = find_val16(g_hist2[4 + q], g_rankin[4 + q], g_topbin[4 + q]);
  if (threadIdx.x == 0){
    float fc = g_frac[2];
    float maxC0 = v[0] * (1.0f - fc) + v[1] * fc;
    float maxC1 = v[2] * (1.0f - fc) + v[3] * fc;
    float s0 = maxCRef[0] / maxC0;
    float s1 = maxCRef[1] / maxC1;
    for (int i = 0; i < 3; i++)
      for (int j = 0; j < 3; j++)
        g_G[i * 3 + j] = HERef[i * 2 + 0] * s0 * g_A[j] + HERef[i * 2 + 1] * s1 * g_A[3 + j];
  }
}

// ---------------- pass 11: final output ----------------
__global__ void __launch_bounds__(256) k_final(const float* __restrict__ img, float* __restrict__ out, int npix){
  int n4 = npix >> 2;
  const float4* R  = (const float4*)img;
  const float4* Gp = R + n4;
  const float4* Bp = R + 2 * n4;
  float4* O = (float4*)out;
  float G00=g_G[0],G01=g_G[1],G02=g_G[2];
  float G10=g_G[3],G11=g_G[4],G12=g_G[5];
  float G20=g_G[6],G21=g_G[7],G22=g_G[8];
  int stride = gridDim.x * blockDim.x;
  for (int i = blockIdx.x * blockDim.x + threadIdx.x; i < n4; i += stride){
    float4 r = R[i], g = Gp[i], b = Bp[i];
    float rr[4] = {r.x, r.y, r.z, r.w};
    float gg[4] = {g.x, g.y, g.z, g.w};
    float bb[4] = {b.x, b.y, b.z, b.w};
    float res[12];
    #pragma unroll
    for (int j = 0; j < 4; j++){
      float o0 = odv(rr[j]), o1 = odv(gg[j]), o2 = odv(bb[j]);
      float y0 = o0*G00 + o1*G01 + o2*G02;
      float y1 = o0*G10 + o1*G11 + o2*G12;
      float y2 = o0*G20 + o1*G21 + o2*G22;
      res[3*j+0] = floorf(fminf(240.0f * expf(-y0), 255.0f)) / 255.0f;
      res[3*j+1] = floorf(fminf(240.0f * expf(-y1), 255.0f)) / 255.0f;
      res[3*j+2] = floorf(fminf(240.0f * expf(-y2), 255.0f)) / 255.0f;
    }
    O[3*i+0] = make_float4(res[0], res[1], res[2],  res[3]);
    O[3*i+1] = make_float4(res[4], res[5], res[6],  res[7]);
    O[3*i+2] = make_float4(res[8], res[9], res[10], res[11]);
  }
}

// ---------------- launch ----------------
extern "C" void kernel_launch(void* const* d_in, const int* in_sizes, int n_in,
                              void* d_out, int out_size) {
  const float* img     = (const float*)d_in[0];
  const float* HERef   = (const float*)d_in[1];
  const float* maxCRef = (const float*)d_in[2];
  float* out = (float*)d_out;
  int npix = in_sizes[0] / 3;
  int n4 = npix >> 2;
  int gBig = (n4 + 255) / 256;

  k_zero   <<<256, 256>>>();
  k_stats  <<<1184, 256>>>(img, npix);
  k_eig    <<<1, 32>>>();
  k_phi    <<<gBig, 256>>>(img, npix);
  k_scan1  <<<1, SCANT>>>();
  k_refine1<<<gBig, 256>>>(npix);
  k_scan2  <<<1, SCANT>>>();
  k_C      <<<gBig, 256>>>(img, npix);
  k_scan3  <<<1, SCANT>>>(npix);
  k_refine2<<<gBig, 256>>>(npix);
  k_scan4  <<<1, SCANT>>>(HERef, maxCRef);
  k_final  <<<gBig, 256>>>(img, out, npix);
}

// round 6
// speedup vs baseline: 1.8956x; 1.8956x over previous
#include <cuda_runtime.h>
#include <stdint.h>

#define NREP 8
#define MAXPIX 4194304
#define SCANT 512      // threads in scan blocks
#define BPT   128      // bins per scan thread (SCANT*BPT = 65536)

// ---------------- device scratch ----------------
__device__ double             g_acc[9];
__device__ unsigned long long g_cnt;
__device__ unsigned           g_hist [NREP][65536];
__device__ unsigned           g_histC0[NREP][65536];
__device__ unsigned           g_histC1[NREP][65536];
__device__ unsigned           g_hist2[8][65536];
__device__ float              g_phi[MAXPIX];
__device__ float              g_c0[MAXPIX];
__device__ float              g_c1[MAXPIX];
__device__ float              g_E[6];        // e_mid(0..2), e_lg(3..5)
__device__ float              g_A[6];        // (HE^T HE)^-1 HE^T   (2x3)
__device__ float              g_G[9];        // fused 3x3
__device__ unsigned           g_topbin[8];
__device__ unsigned           g_rankin[8];
__device__ float              g_frac[3];

// ---------------- helpers ----------------
__device__ __forceinline__ unsigned fkey(float x){
  unsigned u = __float_as_uint(x);
  return (u & 0x80000000u) ? ~u : (u | 0x80000000u);
}
__device__ __forceinline__ unsigned ukey(unsigned u){
  return (u & 0x80000000u) ? ~u : (u | 0x80000000u);
}
__device__ __forceinline__ float keyf(unsigned k){
  return __uint_as_float((k & 0x80000000u) ? (k ^ 0x80000000u) : ~k);
}
__device__ __forceinline__ float odv(float p){
  return -logf((floorf(p * 255.0f) + 1.0f) / 240.0f);
}

// ---------------- zero ----------------
__global__ void __launch_bounds__(256, 1) k_zero(){
  int j = blockIdx.x * blockDim.x + threadIdx.x;
  int stride = gridDim.x * blockDim.x;
  for (int i = j; i < 65536; i += stride){
    #pragma unroll
    for (int r = 0; r < NREP; r++){
      g_hist[r][i] = 0u; g_histC0[r][i] = 0u; g_histC1[r][i] = 0u; g_hist2[r][i] = 0u;
    }
  }
  if (j == 0){
    g_cnt = 0ull;
    for (int k = 0; k < 9; k++) g_acc[k] = 0.0;
  }
}

// ---------------- pass 1: masked stats (f32 per-thread, f64 reduce) ----------------
__global__ void __launch_bounds__(256) k_stats(const float* __restrict__ img, int npix){
  int n4 = npix >> 2;
  const float4* R  = (const float4*)img;
  const float4* Gp = R + n4;
  const float4* Bp = R + 2 * n4;
  float a[9] = {0,0,0,0,0,0,0,0,0};
  unsigned cnt = 0;
  int stride = gridDim.x * blockDim.x;
  for (int i = blockIdx.x * blockDim.x + threadIdx.x; i < n4; i += stride){
    float4 r = R[i], g = Gp[i], b = Bp[i];
    float rr[4] = {r.x, r.y, r.z, r.w};
    float gg[4] = {g.x, g.y, g.z, g.w};
    float bb[4] = {b.x, b.y, b.z, b.w};
    #pragma unroll
    for (int j = 0; j < 4; j++){
      float o0 = odv(rr[j]), o1 = odv(gg[j]), o2 = odv(bb[j]);
      if (o0 >= 0.15f && o1 >= 0.15f && o2 >= 0.15f){
        a[0] += o0; a[1] += o1; a[2] += o2;
        a[3] += o0*o0; a[4] += o0*o1; a[5] += o0*o2;
        a[6] += o1*o1; a[7] += o1*o2; a[8] += o2*o2;
        cnt++;
      }
    }
  }
  // promote to f64 for the reduction tree (few pixels per thread -> f32 partials exact-ish)
  double d[9];
  #pragma unroll
  for (int k = 0; k < 9; k++) d[k] = (double)a[k];
  double c = (double)cnt;
  #pragma unroll
  for (int o = 16; o > 0; o >>= 1){
    #pragma unroll
    for (int k = 0; k < 9; k++) d[k] += __shfl_down_sync(0xffffffffu, d[k], o);
    c += __shfl_down_sync(0xffffffffu, c, o);
  }
  __shared__ double s_acc[10][8];
  int w = threadIdx.x >> 5, lane = threadIdx.x & 31;
  if (lane == 0){
    #pragma unroll
    for (int k = 0; k < 9; k++) s_acc[k][w] = d[k];
    s_acc[9][w] = c;
  }
  __syncthreads();
  if (threadIdx.x == 0){
    int nw = blockDim.x >> 5;
    double t[10] = {0,0,0,0,0,0,0,0,0,0};
    for (int ww = 0; ww < nw; ww++)
      for (int k = 0; k < 10; k++) t[k] += s_acc[k][ww];
    for (int k = 0; k < 9; k++) atomicAdd(&g_acc[k], t[k]);
    atomicAdd(&g_cnt, (unsigned long long)(t[9] + 0.5));
  }
}

// ---------------- pass 2: 3x3 eigh (double Jacobi, 1 thread) ----------------
__global__ void __launch_bounds__(32, 1) k_eig(){
  if (threadIdx.x != 0 || blockIdx.x != 0) return;
  double n = (double)g_cnt;
  double s0 = g_acc[0], s1 = g_acc[1], s2 = g_acc[2];
  double inv = 1.0 / (n - 1.0);
  double a[3][3];
  a[0][0] = (g_acc[3] - s0*s0/n) * inv;
  a[0][1] = a[1][0] = (g_acc[4] - s0*s1/n) * inv;
  a[0][2] = a[2][0] = (g_acc[5] - s0*s2/n) * inv;
  a[1][1] = (g_acc[6] - s1*s1/n) * inv;
  a[1][2] = a[2][1] = (g_acc[7] - s1*s2/n) * inv;
  a[2][2] = (g_acc[8] - s2*s2/n) * inv;
  double V[3][3] = {{1,0,0},{0,1,0},{0,0,1}};
  for (int sweep = 0; sweep < 50; sweep++){
    double off = fabs(a[0][1]) + fabs(a[0][2]) + fabs(a[1][2]);
    if (off == 0.0) break;
    for (int p = 0; p < 2; p++){
      for (int q = p + 1; q < 3; q++){
        double apq = a[p][q];
        if (fabs(apq) < 1e-300) continue;
        double theta = (a[q][q] - a[p][p]) / (2.0 * apq);
        double t = (theta >= 0.0 ? 1.0 : -1.0) / (fabs(theta) + sqrt(theta*theta + 1.0));
        double c = 1.0 / sqrt(t*t + 1.0);
        double s = t * c;
        double app = a[p][p], aqq = a[q][q];
        a[p][p] = app - t * apq;
        a[q][q] = aqq + t * apq;
        a[p][q] = a[q][p] = 0.0;
        int r = 3 - p - q;
        double arp = a[r][p], arq = a[r][q];
        a[r][p] = a[p][r] = c*arp - s*arq;
        a[r][q] = a[q][r] = s*arp + c*arq;
        for (int k = 0; k < 3; k++){
          double vkp = V[k][p], vkq = V[k][q];
          V[k][p] = c*vkp - s*vkq;
          V[k][q] = s*vkp + c*vkq;
        }
      }
    }
  }
  double w[3] = {a[0][0], a[1][1], a[2][2]};
  int idx[3] = {0,1,2};
  for (int i = 0; i < 2; i++)
    for (int j = i + 1; j < 3; j++)
      if (w[idx[j]] < w[idx[i]]){ int tmp = idx[i]; idx[i] = idx[j]; idx[j] = tmp; }
  int cols[2] = {idx[1], idx[2]};   // middle, largest eigenvalue
  for (int j = 0; j < 2; j++){
    double v0 = V[0][cols[j]], v1 = V[1][cols[j]], v2 = V[2][cols[j]];
    double mx = v0, mxa = fabs(v0);
    if (fabs(v1) > mxa){ mxa = fabs(v1); mx = v1; }
    if (fabs(v2) > mxa){ mxa = fabs(v2); mx = v2; }
    double sgn = (mx < 0.0) ? -1.0 : 1.0;   // sign convention (flip candidate)
    g_E[3*j+0] = (float)(v0 * sgn);
    g_E[3*j+1] = (float)(v1 * sgn);
    g_E[3*j+2] = (float)(v2 * sgn);
  }
}

// ---------------- pass 3: phi + top-16 histogram ----------------
__global__ void __launch_bounds__(256) k_phi(const float* __restrict__ img, int npix){
  int n4 = npix >> 2;
  const float4* R  = (const float4*)img;
  const float4* Gp = R + n4;
  const float4* Bp = R + 2 * n4;
  float4* PH = (float4*)g_phi;
  float e0=g_E[0],e1=g_E[1],e2=g_E[2],e3=g_E[3],e4=g_E[4],e5=g_E[5];
  unsigned rep = blockIdx.x & (NREP - 1);
  int stride = gridDim.x * blockDim.x;
  for (int i = blockIdx.x * blockDim.x + threadIdx.x; i < n4; i += stride){
    float4 r = R[i], g = Gp[i], b = Bp[i];
    float rr[4] = {r.x, r.y, r.z, r.w};
    float gg[4] = {g.x, g.y, g.z, g.w};
    float bb[4] = {b.x, b.y, b.z, b.w};
    float ph[4];
    #pragma unroll
    for (int j = 0; j < 4; j++){
      float o0 = odv(rr[j]), o1 = odv(gg[j]), o2 = odv(bb[j]);
      if (o0 >= 0.15f && o1 >= 0.15f && o2 >= 0.15f){
        float t0 = o0*e0 + o1*e1 + o2*e2;
        float t1 = o0*e3 + o1*e4 + o2*e5;
        float p = atan2f(t1, t0);
        ph[j] = p;
        atomicAdd(&g_hist[rep][fkey(p) >> 16], 1u);
      } else {
        ph[j] = __int_as_float(0x7f800000);   // +inf: sorts last, never histogrammed
      }
    }
    PH[i] = make_float4(ph[0], ph[1], ph[2], ph[3]);
  }
}

// ---------------- block scan infra (blockDim == SCANT) ----------------
__device__ unsigned blk_exscan(unsigned v){
  __shared__ unsigned ws[32];
  unsigned lane = threadIdx.x & 31, w = threadIdx.x >> 5;
  unsigned x = v;
  #pragma unroll
  for (int o = 1; o < 32; o <<= 1){
    unsigned y = __shfl_up_sync(0xffffffffu, x, o);
    if (lane >= o) x += y;
  }
  if (lane == 31) ws[w] = x;
  __syncthreads();
  if (threadIdx.x < 32){
    unsigned t = (lane < (SCANT / 32)) ? ws[lane] : 0u;
    #pragma unroll
    for (int o = 1; o < 32; o <<= 1){
      unsigned y = __shfl_up_sync(0xffffffffu, t, o);
      if (lane >= o) t += y;
    }
    ws[lane] = t;
  }
  __syncthreads();
  unsigned base = (w == 0) ? 0u : ws[w - 1];
  unsigned res = base + x - v;
  __syncthreads();
  return res;
}

__device__ __forceinline__ unsigned sumrep(const unsigned (*h)[65536], unsigned bin){
  unsigned s = 0;
  #pragma unroll
  for (int r = 0; r < NREP; r++) s += h[r][bin];
  return s;
}

// find multiple k-th order stats over an NREP-replicated histogram in ONE read pass
__device__ void find_kth_multi(const unsigned (*hist)[65536], const unsigned* ranks, int nr,
                               unsigned* out_bin, unsigned* out_rib){
  unsigned base = threadIdx.x * BPT;
  unsigned s = 0;
  for (int b = 0; b < BPT; b++) s += sumrep(hist, base + b);
  unsigned cum = blk_exscan(s);
  for (int q = 0; q < nr; q++){
    unsigned rank = ranks[q];
    if (rank >= cum && rank < cum + s){
      unsigned c2 = cum;
      for (int b = 0; b < BPT; b++){
        unsigned h = sumrep(hist, base + b);
        if (rank < c2 + h){ out_bin[q] = base + b; out_rib[q] = rank - c2; break; }
        c2 += h;
      }
    }
  }
  __syncthreads();
}

// find k-th over a plain 65536-bin low-16 histogram, return reconstructed float
__device__ float find_val16(const unsigned* __restrict__ hist, unsigned rank, unsigned topbin){
  __shared__ float s_val;
  unsigned base = threadIdx.x * BPT;
  unsigned s = 0;
  for (int b = 0; b < BPT; b++) s += hist[base + b];
  unsigned cum = blk_exscan(s);
  if (rank >= cum && rank < cum + s){
    for (int b = 0; b < BPT; b++){
      unsigned h = hist[base + b];
      if (rank < cum + h){ s_val = keyf((topbin << 16) | (base + b)); break; }
      cum += h;
    }
  }
  __syncthreads();
  float v = s_val;
  __syncthreads();
  return v;
}

// ---------------- pass 4: phi quantile top bins ----------------
__global__ void __launch_bounds__(SCANT, 1) k_scan1(){
  __shared__ unsigned sh_rank[4];
  if (threadIdx.x == 0){
    unsigned n = (unsigned)g_cnt;
    float nm1 = (float)(n - 1u);
    float p0 = 0.01f * nm1, p1 = 0.99f * nm1;
    float l0 = floorf(p0), l1 = floorf(p1);
    sh_rank[0] = (unsigned)l0; sh_rank[1] = (unsigned)ceilf(p0);
    sh_rank[2] = (unsigned)l1; sh_rank[3] = (unsigned)ceilf(p1);
    g_frac[0] = p0 - l0; g_frac[1] = p1 - l1;
  }
  __syncthreads();
  find_kth_multi(g_hist, sh_rank, 4, &g_topbin[0], &g_rankin[0]);
}

// ---------------- pass 5: phi refine ----------------
__global__ void __launch_bounds__(256) k_refine1(int npix){
  const uint4* P = (const uint4*)g_phi;
  unsigned tb0 = g_topbin[0], tb1 = g_topbin[1], tb2 = g_topbin[2], tb3 = g_topbin[3];
  int n4 = npix >> 2;
  int stride = gridDim.x * blockDim.x;
  for (int i = blockIdx.x * blockDim.x + threadIdx.x; i < n4; i += stride){
    uint4 u = P[i];
    unsigned kk[4] = {ukey(u.x), ukey(u.y), ukey(u.z), ukey(u.w)};
    #pragma unroll
    for (int j = 0; j < 4; j++){
      unsigned top = kk[j] >> 16, low = kk[j] & 0xffffu;
      if (top == tb0) atomicAdd(&g_hist2[0][low], 1u);
      if (top == tb1) atomicAdd(&g_hist2[1][low], 1u);
      if (top == tb2) atomicAdd(&g_hist2[2][low], 1u);
      if (top == tb3) atomicAdd(&g_hist2[3][low], 1u);
    }
  }
}

// ---------------- pass 6: HE + solve matrix ----------------
__global__ void __launch_bounds__(SCANT, 1) k_scan2(){
  float v[4];
  for (int q = 0; q < 4; q++)
    v[q] = find_val16(g_hist2[q], g_rankin[q], g_topbin[q]);
  if (threadIdx.x == 0){
    float f0 = g_frac[0], f1 = g_frac[1];
    float minPhi = v[0] * (1.0f - f0) + v[1] * f0;
    float maxPhi = v[2] * (1.0f - f1) + v[3] * f1;
    float cmn = cosf(minPhi), smn = sinf(minPhi);
    float cmx = cosf(maxPhi), smx = sinf(maxPhi);
    float vMin[3], vMax[3];
    for (int i = 0; i < 3; i++){
      vMin[i] = g_E[i] * cmn + g_E[3 + i] * smn;
      vMax[i] = g_E[i] * cmx + g_E[3 + i] * smx;
    }
    float he[3][2];
    if (vMin[0] > vMax[0])
      for (int i = 0; i < 3; i++){ he[i][0] = vMin[i]; he[i][1] = vMax[i]; }
    else
      for (int i = 0; i < 3; i++){ he[i][0] = vMax[i]; he[i][1] = vMin[i]; }
    double m00 = 0, m01 = 0, m11 = 0;
    for (int i = 0; i < 3; i++){
      m00 += (double)he[i][0] * he[i][0];
      m01 += (double)he[i][0] * he[i][1];
      m11 += (double)he[i][1] * he[i][1];
    }
    double det = m00 * m11 - m01 * m01;
    double i00 = m11 / det, i01 = -m01 / det, i11 = m00 / det;
    for (int j = 0; j < 3; j++){
      g_A[j]     = (float)(i00 * he[j][0] + i01 * he[j][1]);
      g_A[3 + j] = (float)(i01 * he[j][0] + i11 * he[j][1]);
    }
  }
}

// ---------------- pass 7: C + histograms ----------------
__global__ void __launch_bounds__(256) k_C(const float* __restrict__ img, int npix){
  int n4 = npix >> 2;
  const float4* R  = (const float4*)img;
  const float4* Gp = R + n4;
  const float4* Bp = R + 2 * n4;
  float4* C0 = (float4*)g_c0;
  float4* C1 = (float4*)g_c1;
  float a0=g_A[0],a1=g_A[1],a2=g_A[2],a3=g_A[3],a4=g_A[4],a5=g_A[5];
  unsigned rep = blockIdx.x & (NREP - 1);
  int stride = gridDim.x * blockDim.x;
  for (int i = blockIdx.x * blockDim.x + threadIdx.x; i < n4; i += stride){
    float4 r = R[i], g = Gp[i], b = Bp[i];
    float rr[4] = {r.x, r.y, r.z, r.w};
    float gg[4] = {g.x, g.y, g.z, g.w};
    float bb[4] = {b.x, b.y, b.z, b.w};
    float c0v[4], c1v[4];
    #pragma unroll
    for (int j = 0; j < 4; j++){
      float o0 = odv(rr[j]), o1 = odv(gg[j]), o2 = odv(bb[j]);
      float c0 = o0*a0 + o1*a1 + o2*a2;
      float c1 = o0*a3 + o1*a4 + o2*a5;
      c0v[j] = c0; c1v[j] = c1;
      atomicAdd(&g_histC0[rep][fkey(c0) >> 16], 1u);
      atomicAdd(&g_histC1[rep][fkey(c1) >> 16], 1u);
    }
    C0[i] = make_float4(c0v[0], c0v[1], c0v[2], c0v[3]);
    C1[i] = make_float4(c1v[0], c1v[1], c1v[2], c1v[3]);
  }
}

// ---------------- pass 8: C quantile top bins ----------------
__global__ void __launch_bounds__(SCANT, 1) k_scan3(int npix){
  __shared__ unsigned sh_rank[2];
  if (threadIdx.x == 0){
    float nm1 = (float)(npix - 1);
    float p = 0.99f * nm1;
    float l = floorf(p);
    sh_rank[0] = (unsigned)l;
    sh_rank[1] = (unsigned)ceilf(p);
    g_frac[2] = p - l;
  }
  __syncthreads();
  find_kth_multi(g_histC0, sh_rank, 2, &g_topbin[4], &g_rankin[4]);
  find_kth_multi(g_histC1, sh_rank, 2, &g_topbin[6], &g_rankin[6]);
}

// ---------------- pass 9: C refine ----------------
__global__ void __launch_bounds__(256) k_refine2(int npix){
  const uint4* P0 = (const uint4*)g_c0;
  const uint4* P1 = (const uint4*)g_c1;
  unsigned tb4 = g_topbin[4], tb5 = g_topbin[5], tb6 = g_topbin[6], tb7 = g_topbin[7];
  int n4 = npix >> 2;
  int stride = gridDim.x * blockDim.x;
  for (int i = blockIdx.x * blockDim.x + threadIdx.x; i < n4; i += stride){
    uint4 u0 = P0[i], u1 = P1[i];
    unsigned k0[4] = {ukey(u0.x), ukey(u0.y), ukey(u0.z), ukey(u0.w)};
    unsigned k1[4] = {ukey(u1.x), ukey(u1.y), ukey(u1.z), ukey(u1.w)};
    #pragma unroll
    for (int j = 0; j < 4; j++){
      unsigned t0 = k0[j] >> 16, l0 = k0[j] & 0xffffu;
      unsigned t1 = k1[j] >> 16, l1 = k1[j] & 0xffffu;
      if (t0 == tb4) atomicAdd(&g_hist2[4][l0], 1u);
      if (t0 == tb5) atomicAdd(&g_hist2[5][l0], 1u);
      if (t1 == tb6) atomicAdd(&g_hist2[6][l1], 1u);
      if (t1 == tb7) atomicAdd(&g_hist2[7][l1], 1u);
    }
  }
}

// ---------------- pass 10: fuse G ----------------
__global__ void __launch_bounds__(SCANT, 1) k_scan4(const float* __restrict__ HERef, const float* __restrict__ maxCRef){
  float v[4];
  for (int q = 0; q < 4; q++)
    v[q] = find_val16(g_hist2[4 + q], g_rankin[4 + q], g_topbin[4 + q]);
  if (threadIdx.x == 0){
    float fc = g_frac[2];
    float maxC0 = v[0] * (1.0f - fc) + v[1] * fc;
    float maxC1 = v[2] * (1.0f - fc) + v[3] * fc;
    float s0 = maxCRef[0] / maxC0;
    float s1 = maxCRef[1] / maxC1;
    for (int i = 0; i < 3; i++)
      for (int j = 0; j < 3; j++)
        g_G[i * 3 + j] = HERef[i * 2 + 0] * s0 * g_A[j] + HERef[i * 2 + 1] * s1 * g_A[3 + j];
  }
}

// ---------------- pass 11: final output ----------------
__global__ void __launch_bounds__(256) k_final(const float* __restrict__ img, float* __restrict__ out, int npix){
  int n4 = npix >> 2;
  const float4* R  = (const float4*)img;
  const float4* Gp = R + n4;
  const float4* Bp = R + 2 * n4;
  float4* O = (float4*)out;
  float G00=g_G[0],G01=g_G[1],G02=g_G[2];
  float G10=g_G[3],G11=g_G[4],G12=g_G[5];
  float G20=g_G[6],G21=g_G[7],G22=g_G[8];
  int stride = gridDim.x * blockDim.x;
  for (int i = blockIdx.x * blockDim.x + threadIdx.x; i < n4; i += stride){
    float4 r = R[i], g = Gp[i], b = Bp[i];
    float rr[4] = {r.x, r.y, r.z, r.w};
    float gg[4] = {g.x, g.y, g.z, g.w};
    float bb[4] = {b.x, b.y, b.z, b.w};
    float res[12];
    #pragma unroll
    for (int j = 0; j < 4; j++){
      float o0 = odv(rr[j]), o1 = odv(gg[j]), o2 = odv(bb[j]);
      float y0 = o0*G00 + o1*G01 + o2*G02;
      float y1 = o0*G10 + o1*G11 + o2*G12;
      float y2 = o0*G20 + o1*G21 + o2*G22;
      res[3*j+0] = floorf(fminf(240.0f * expf(-y0), 255.0f)) / 255.0f;
      res[3*j+1] = floorf(fminf(240.0f * expf(-y1), 255.0f)) / 255.0f;
      res[3*j+2] = floorf(fminf(240.0f * expf(-y2), 255.0f)) / 255.0f;
    }
    O[3*i+0] = make_float4(res[0], res[1], res[2],  res[3]);
    O[3*i+1] = make_float4(res[4], res[5], res[6],  res[7]);
    O[3*i+2] = make_float4(res[8], res[9], res[10], res[11]);
  }
}

// ---------------- launch ----------------
extern "C" void kernel_launch(void* const* d_in, const int* in_sizes, int n_in,
                              void* d_out, int out_size) {
  const float* img     = (const float*)d_in[0];
  const float* HERef   = (const float*)d_in[1];
  const float* maxCRef = (const float*)d_in[2];
  float* out = (float*)d_out;
  int npix = in_sizes[0] / 3;
  int n4 = npix >> 2;
  int gBig = (n4 + 255) / 256;

  k_zero   <<<256, 256>>>();
  k_stats  <<<gBig, 256>>>(img, npix);
  k_eig    <<<1, 32>>>();
  k_phi    <<<gBig, 256>>>(img, npix);
  k_scan1  <<<1, SCANT>>>();
  k_refine1<<<gBig, 256>>>(npix);
  k_scan2  <<<1, SCANT>>>();
  k_C      <<<gBig, 256>>>(img, npix);
  k_scan3  <<<1, SCANT>>>(npix);
  k_refine2<<<gBig, 256>>>(npix);
  k_scan4  <<<1, SCANT>>>(HERef, maxCRef);
  k_final  <<<gBig, 256>>>(img, out, npix);
}

// round 7
// speedup vs baseline: 1.9152x; 1.0104x over previous
#include <cuda_runtime.h>
#include <stdint.h>

#define MAXPIX 4194304
#define SCANT 512
#define L1BINS 4096
#define L2BINS (1 << 20)

// ---------------- device scratch ----------------
__device__ double             g_acc[9];
__device__ unsigned long long g_cnt;
__device__ unsigned           g_histP [L1BINS];
__device__ unsigned           g_histC0[L1BINS];
__device__ unsigned           g_histC1[L1BINS];
__device__ unsigned           g_big[8][L2BINS];   // 32 MB L2-refine histograms
__device__ float              g_phi[MAXPIX];
__device__ float              g_c0[MAXPIX];
__device__ float              g_c1[MAXPIX];
__device__ float              g_E[6];        // e_mid(0..2), e_lg(3..5)
__device__ float              g_A[6];        // (HE^T HE)^-1 HE^T   (2x3)
__device__ float              g_G[9];        // fused 3x3
__device__ unsigned           g_topbin[8];
__device__ unsigned           g_rankin[8];
__device__ float              g_frac[3];

// ---------------- helpers ----------------
__device__ __forceinline__ unsigned fkey(float x){
  unsigned u = __float_as_uint(x);
  return (u & 0x80000000u) ? ~u : (u | 0x80000000u);
}
__device__ __forceinline__ unsigned ukey(unsigned u){
  return (u & 0x80000000u) ? ~u : (u | 0x80000000u);
}
__device__ __forceinline__ float keyf(unsigned k){
  return __uint_as_float((k & 0x80000000u) ? (k ^ 0x80000000u) : ~k);
}
__device__ __forceinline__ float odv(float p){
  return -logf((floorf(p * 255.0f) + 1.0f) / 240.0f);
}

// ---------------- zero ----------------
__global__ void __launch_bounds__(256, 1) k_zero(){
  int tid = blockIdx.x * blockDim.x + threadIdx.x;
  int stride = gridDim.x * blockDim.x;
  uint4 z = make_uint4(0, 0, 0, 0);
  uint4* B = (uint4*)&g_big[0][0];
  int tot4 = (8 * L2BINS) / 4;
  for (int i = tid; i < tot4; i += stride) B[i] = z;
  if (tid < L1BINS){
    g_histP[tid] = 0u; g_histC0[tid] = 0u; g_histC1[tid] = 0u;
  }
  if (tid == 0){
    g_cnt = 0ull;
    for (int k = 0; k < 9; k++) g_acc[k] = 0.0;
  }
}

// ---------------- pass 1: masked stats (f32 per-thread, f64 reduce) ----------------
__global__ void __launch_bounds__(256) k_stats(const float* __restrict__ img, int npix){
  int n4 = npix >> 2;
  const float4* R  = (const float4*)img;
  const float4* Gp = R + n4;
  const float4* Bp = R + 2 * n4;
  float a[9] = {0,0,0,0,0,0,0,0,0};
  unsigned cnt = 0;
  int stride = gridDim.x * blockDim.x;
  for (int i = blockIdx.x * blockDim.x + threadIdx.x; i < n4; i += stride){
    float4 r = R[i], g = Gp[i], b = Bp[i];
    float rr[4] = {r.x, r.y, r.z, r.w};
    float gg[4] = {g.x, g.y, g.z, g.w};
    float bb[4] = {b.x, b.y, b.z, b.w};
    #pragma unroll
    for (int j = 0; j < 4; j++){
      float o0 = odv(rr[j]), o1 = odv(gg[j]), o2 = odv(bb[j]);
      if (o0 >= 0.15f && o1 >= 0.15f && o2 >= 0.15f){
        a[0] += o0; a[1] += o1; a[2] += o2;
        a[3] += o0*o0; a[4] += o0*o1; a[5] += o0*o2;
        a[6] += o1*o1; a[7] += o1*o2; a[8] += o2*o2;
        cnt++;
      }
    }
  }
  double d[9];
  #pragma unroll
  for (int k = 0; k < 9; k++) d[k] = (double)a[k];
  double c = (double)cnt;
  #pragma unroll
  for (int o = 16; o > 0; o >>= 1){
    #pragma unroll
    for (int k = 0; k < 9; k++) d[k] += __shfl_down_sync(0xffffffffu, d[k], o);
    c += __shfl_down_sync(0xffffffffu, c, o);
  }
  __shared__ double s_acc[10][8];
  int w = threadIdx.x >> 5, lane = threadIdx.x & 31;
  if (lane == 0){
    #pragma unroll
    for (int k = 0; k < 9; k++) s_acc[k][w] = d[k];
    s_acc[9][w] = c;
  }
  __syncthreads();
  if (threadIdx.x == 0){
    int nw = blockDim.x >> 5;
    double t[10] = {0,0,0,0,0,0,0,0,0,0};
    for (int ww = 0; ww < nw; ww++)
      for (int k = 0; k < 10; k++) t[k] += s_acc[k][ww];
    for (int k = 0; k < 9; k++) atomicAdd(&g_acc[k], t[k]);
    atomicAdd(&g_cnt, (unsigned long long)(t[9] + 0.5));
  }
}

// ---------------- pass 2: 3x3 eigh (double Jacobi, 1 thread) ----------------
__global__ void __launch_bounds__(32, 1) k_eig(){
  if (threadIdx.x != 0 || blockIdx.x != 0) return;
  double n = (double)g_cnt;
  double s0 = g_acc[0], s1 = g_acc[1], s2 = g_acc[2];
  double inv = 1.0 / (n - 1.0);
  double a[3][3];
  a[0][0] = (g_acc[3] - s0*s0/n) * inv;
  a[0][1] = a[1][0] = (g_acc[4] - s0*s1/n) * inv;
  a[0][2] = a[2][0] = (g_acc[5] - s0*s2/n) * inv;
  a[1][1] = (g_acc[6] - s1*s1/n) * inv;
  a[1][2] = a[2][1] = (g_acc[7] - s1*s2/n) * inv;
  a[2][2] = (g_acc[8] - s2*s2/n) * inv;
  double V[3][3] = {{1,0,0},{0,1,0},{0,0,1}};
  for (int sweep = 0; sweep < 50; sweep++){
    double off = fabs(a[0][1]) + fabs(a[0][2]) + fabs(a[1][2]);
    if (off == 0.0) break;
    for (int p = 0; p < 2; p++){
      for (int q = p + 1; q < 3; q++){
        double apq = a[p][q];
        if (fabs(apq) < 1e-300) continue;
        double theta = (a[q][q] - a[p][p]) / (2.0 * apq);
        double t = (theta >= 0.0 ? 1.0 : -1.0) / (fabs(theta) + sqrt(theta*theta + 1.0));
        double c = 1.0 / sqrt(t*t + 1.0);
        double s = t * c;
        double app = a[p][p], aqq = a[q][q];
        a[p][p] = app - t * apq;
        a[q][q] = aqq + t * apq;
        a[p][q] = a[q][p] = 0.0;
        int r = 3 - p - q;
        double arp = a[r][p], arq = a[r][q];
        a[r][p] = a[p][r] = c*arp - s*arq;
        a[r][q] = a[q][r] = s*arp + c*arq;
        for (int k = 0; k < 3; k++){
          double vkp = V[k][p], vkq = V[k][q];
          V[k][p] = c*vkp - s*vkq;
          V[k][q] = s*vkp + c*vkq;
        }
      }
    }
  }
  double w[3] = {a[0][0], a[1][1], a[2][2]};
  int idx[3] = {0,1,2};
  for (int i = 0; i < 2; i++)
    for (int j = i + 1; j < 3; j++)
      if (w[idx[j]] < w[idx[i]]){ int tmp = idx[i]; idx[i] = idx[j]; idx[j] = tmp; }
  int cols[2] = {idx[1], idx[2]};   // middle, largest eigenvalue
  for (int j = 0; j < 2; j++){
    double v0 = V[0][cols[j]], v1 = V[1][cols[j]], v2 = V[2][cols[j]];
    double mx = v0, mxa = fabs(v0);
    if (fabs(v1) > mxa){ mxa = fabs(v1); mx = v1; }
    if (fabs(v2) > mxa){ mxa = fabs(v2); mx = v2; }
    double sgn = (mx < 0.0) ? -1.0 : 1.0;
    g_E[3*j+0] = (float)(v0 * sgn);
    g_E[3*j+1] = (float)(v1 * sgn);
    g_E[3*j+2] = (float)(v2 * sgn);
  }
}

// ---------------- pass 3: phi + 12-bit smem histogram ----------------
__global__ void __launch_bounds__(256) k_phi(const float* __restrict__ img, int npix){
  __shared__ unsigned sh[L1BINS];
  for (int b = threadIdx.x; b < L1BINS; b += 256) sh[b] = 0u;
  __syncthreads();
  int n4 = npix >> 2;
  const float4* R  = (const float4*)img;
  const float4* Gp = R + n4;
  const float4* Bp = R + 2 * n4;
  float4* PH = (float4*)g_phi;
  float e0=g_E[0],e1=g_E[1],e2=g_E[2],e3=g_E[3],e4=g_E[4],e5=g_E[5];
  int stride = gridDim.x * blockDim.x;
  for (int i = blockIdx.x * blockDim.x + threadIdx.x; i < n4; i += stride){
    float4 r = R[i], g = Gp[i], b = Bp[i];
    float rr[4] = {r.x, r.y, r.z, r.w};
    float gg[4] = {g.x, g.y, g.z, g.w};
    float bb[4] = {b.x, b.y, b.z, b.w};
    float ph[4];
    #pragma unroll
    for (int j = 0; j < 4; j++){
      float o0 = odv(rr[j]), o1 = odv(gg[j]), o2 = odv(bb[j]);
      if (o0 >= 0.15f && o1 >= 0.15f && o2 >= 0.15f){
        float t0 = o0*e0 + o1*e1 + o2*e2;
        float t1 = o0*e3 + o1*e4 + o2*e5;
        float p = atan2f(t1, t0);
        ph[j] = p;
        atomicAdd(&sh[fkey(p) >> 20], 1u);
      } else {
        ph[j] = __int_as_float(0x7f800000);   // +inf: sorts last, never histogrammed
      }
    }
    PH[i] = make_float4(ph[0], ph[1], ph[2], ph[3]);
  }
  __syncthreads();
  for (int b = threadIdx.x; b < L1BINS; b += 256){
    unsigned v = sh[b];
    if (v) atomicAdd(&g_histP[b], v);
  }
}

// ---------------- block scan infra (blockDim == SCANT) ----------------
__device__ unsigned blk_exscan(unsigned v){
  __shared__ unsigned ws[32];
  unsigned lane = threadIdx.x & 31, w = threadIdx.x >> 5;
  unsigned x = v;
  #pragma unroll
  for (int o = 1; o < 32; o <<= 1){
    unsigned y = __shfl_up_sync(0xffffffffu, x, o);
    if (lane >= o) x += y;
  }
  if (lane == 31) ws[w] = x;
  __syncthreads();
  if (threadIdx.x < 32){
    unsigned t = (lane < (SCANT / 32)) ? ws[lane] : 0u;
    #pragma unroll
    for (int o = 1; o < 32; o <<= 1){
      unsigned y = __shfl_up_sync(0xffffffffu, t, o);
      if (lane >= o) t += y;
    }
    ws[lane] = t;
  }
  __syncthreads();
  unsigned base = (w == 0) ? 0u : ws[w - 1];
  unsigned res = base + x - v;
  __syncthreads();
  return res;
}

// find multiple k-th over a 4096-bin L1 histogram (one read pass)
__device__ void find_kth_l1(const unsigned* __restrict__ hist, const unsigned* ranks, int nr,
                            unsigned* out_bin, unsigned* out_rib){
  unsigned base = threadIdx.x * (L1BINS / SCANT);   // 8 bins/thread
  unsigned h[L1BINS / SCANT];
  unsigned s = 0;
  #pragma unroll
  for (int b = 0; b < L1BINS / SCANT; b++){ h[b] = hist[base + b]; s += h[b]; }
  unsigned cum = blk_exscan(s);
  for (int q = 0; q < nr; q++){
    unsigned rank = ranks[q];
    if (rank >= cum && rank < cum + s){
      unsigned c2 = cum;
      #pragma unroll
      for (int b = 0; b < L1BINS / SCANT; b++){
        if (rank < c2 + h[b]){ out_bin[q] = base + b; out_rib[q] = rank - c2; break; }
        c2 += h[b];
      }
    }
  }
  __syncthreads();
}

// find k-th over a 1M-bin L2 histogram (uint4-vectorized), return reconstructed float
__device__ float find_val20(const unsigned* __restrict__ hist, unsigned rank, unsigned topbin){
  __shared__ float s_val;
  const uint4* H = (const uint4*)hist;
  const int per = (L2BINS / SCANT) / 4;   // 512 uint4 per thread
  unsigned base4 = threadIdx.x * per;
  unsigned s = 0;
  for (int b = 0; b < per; b++){
    uint4 u = H[base4 + b];
    s += u.x + u.y + u.z + u.w;
  }
  unsigned cum = blk_exscan(s);
  if (rank >= cum && rank < cum + s){
    unsigned c2 = cum;
    for (int b = 0; b < per; b++){
      uint4 u = H[base4 + b];
      unsigned bin = (base4 + b) * 4;
      if (rank < c2 + u.x){ s_val = keyf((topbin << 20) | (bin + 0)); break; } c2 += u.x;
      if (rank < c2 + u.y){ s_val = keyf((topbin << 20) | (bin + 1)); break; } c2 += u.y;
      if (rank < c2 + u.z){ s_val = keyf((topbin << 20) | (bin + 2)); break; } c2 += u.z;
      if (rank < c2 + u.w){ s_val = keyf((topbin << 20) | (bin + 3)); break; } c2 += u.w;
    }
  }
  __syncthreads();
  float v = s_val;
  __syncthreads();
  return v;
}

// ---------------- pass 4: phi quantile top bins ----------------
__global__ void __launch_bounds__(SCANT, 1) k_scan1(){
  __shared__ unsigned sh_rank[4];
  if (threadIdx.x == 0){
    unsigned n = (unsigned)g_cnt;
    float nm1 = (float)(n - 1u);
    float p0 = 0.01f * nm1, p1 = 0.99f * nm1;
    float l0 = floorf(p0), l1 = floorf(p1);
    sh_rank[0] = (unsigned)l0; sh_rank[1] = (unsigned)ceilf(p0);
    sh_rank[2] = (unsigned)l1; sh_rank[3] = (unsigned)ceilf(p1);
    g_frac[0] = p0 - l0; g_frac[1] = p1 - l1;
  }
  __syncthreads();
  find_kth_l1(g_histP, sh_rank, 4, &g_topbin[0], &g_rankin[0]);
}

// ---------------- pass 5: phi refine (20-bit) ----------------
__global__ void __launch_bounds__(256) k_refine1(int npix){
  const uint4* P = (const uint4*)g_phi;
  unsigned tb0 = g_topbin[0], tb1 = g_topbin[1], tb2 = g_topbin[2], tb3 = g_topbin[3];
  int n4 = npix >> 2;
  int stride = gridDim.x * blockDim.x;
  for (int i = blockIdx.x * blockDim.x + threadIdx.x; i < n4; i += stride){
    uint4 u = P[i];
    unsigned kk[4] = {ukey(u.x), ukey(u.y), ukey(u.z), ukey(u.w)};
    #pragma unroll
    for (int j = 0; j < 4; j++){
      unsigned top = kk[j] >> 20, low = kk[j] & 0xFFFFFu;
      if (top == tb0) atomicAdd(&g_big[0][low], 1u);
      if (top == tb1) atomicAdd(&g_big[1][low], 1u);
      if (top == tb2) atomicAdd(&g_big[2][low], 1u);
      if (top == tb3) atomicAdd(&g_big[3][low], 1u);
    }
  }
}

// ---------------- pass 6: HE + solve matrix ----------------
__global__ void __launch_bounds__(SCANT, 1) k_scan2(){
  float v[4];
  for (int q = 0; q < 4; q++)
    v[q] = find_val20(g_big[q], g_rankin[q], g_topbin[q]);
  if (threadIdx.x == 0){
    float f0 = g_frac[0], f1 = g_frac[1];
    float minPhi = v[0] * (1.0f - f0) + v[1] * f0;
    float maxPhi = v[2] * (1.0f - f1) + v[3] * f1;
    float cmn = cosf(minPhi), smn = sinf(minPhi);
    float cmx = cosf(maxPhi), smx = sinf(maxPhi);
    float vMin[3], vMax[3];
    for (int i = 0; i < 3; i++){
      vMin[i] = g_E[i] * cmn + g_E[3 + i] * smn;
      vMax[i] = g_E[i] * cmx + g_E[3 + i] * smx;
    }
    float he[3][2];
    if (vMin[0] > vMax[0])
      for (int i = 0; i < 3; i++){ he[i][0] = vMin[i]; he[i][1] = vMax[i]; }
    else
      for (int i = 0; i < 3; i++){ he[i][0] = vMax[i]; he[i][1] = vMin[i]; }
    double m00 = 0, m01 = 0, m11 = 0;
    for (int i = 0; i < 3; i++){
      m00 += (double)he[i][0] * he[i][0];
      m01 += (double)he[i][0] * he[i][1];
      m11 += (double)he[i][1] * he[i][1];
    }
    double det = m00 * m11 - m01 * m01;
    double i00 = m11 / det, i01 = -m01 / det, i11 = m00 / det;
    for (int j = 0; j < 3; j++){
      g_A[j]     = (float)(i00 * he[j][0] + i01 * he[j][1]);
      g_A[3 + j] = (float)(i01 * he[j][0] + i11 * he[j][1]);
    }
  }
}

// ---------------- pass 7: C + 12-bit smem histograms ----------------
__global__ void __launch_bounds__(256) k_C(const float* __restrict__ img, int npix){
  __shared__ unsigned sh0[L1BINS];
  __shared__ unsigned sh1[L1BINS];
  for (int b = threadIdx.x; b < L1BINS; b += 256){ sh0[b] = 0u; sh1[b] = 0u; }
  __syncthreads();
  int n4 = npix >> 2;
  const float4* R  = (const float4*)img;
  const float4* Gp = R + n4;
  const float4* Bp = R + 2 * n4;
  float4* C0 = (float4*)g_c0;
  float4* C1 = (float4*)g_c1;
  float a0=g_A[0],a1=g_A[1],a2=g_A[2],a3=g_A[3],a4=g_A[4],a5=g_A[5];
  int stride = gridDim.x * blockDim.x;
  for (int i = blockIdx.x * blockDim.x + threadIdx.x; i < n4; i += stride){
    float4 r = R[i], g = Gp[i], b = Bp[i];
    float rr[4] = {r.x, r.y, r.z, r.w};
    float gg[4] = {g.x, g.y, g.z, g.w};
    float bb[4] = {b.x, b.y, b.z, b.w};
    float c0v[4], c1v[4];
    #pragma unroll
    for (int j = 0; j < 4; j++){
      float o0 = odv(rr[j]), o1 = odv(gg[j]), o2 = odv(bb[j]);
      float c0 = o0*a0 + o1*a1 + o2*a2;
      float c1 = o0*a3 + o1*a4 + o2*a5;
      c0v[j] = c0; c1v[j] = c1;
      atomicAdd(&sh0[fkey(c0) >> 20], 1u);
      atomicAdd(&sh1[fkey(c1) >> 20], 1u);
    }
    C0[i] = make_float4(c0v[0], c0v[1], c0v[2], c0v[3]);
    C1[i] = make_float4(c1v[0], c1v[1], c1v[2], c1v[3]);
  }
  __syncthreads();
  for (int b = threadIdx.x; b < L1BINS; b += 256){
    unsigned v0 = sh0[b]; if (v0) atomicAdd(&g_histC0[b], v0);
    unsigned v1 = sh1[b]; if (v1) atomicAdd(&g_histC1[b], v1);
  }
}

// ---------------- pass 8: C quantile top bins ----------------
__global__ void __launch_bounds__(SCANT, 1) k_scan3(int npix){
  __shared__ unsigned sh_rank[2];
  if (threadIdx.x == 0){
    float nm1 = (float)(npix - 1);
    float p = 0.99f * nm1;
    float l = floorf(p);
    sh_rank[0] = (unsigned)l;
    sh_rank[1] = (unsigned)ceilf(p);
    g_frac[2] = p - l;
  }
  __syncthreads();
  find_kth_l1(g_histC0, sh_rank, 2, &g_topbin[4], &g_rankin[4]);
  find_kth_l1(g_histC1, sh_rank, 2, &g_topbin[6], &g_rankin[6]);
}

// ---------------- pass 9: C refine (20-bit) ----------------
__global__ void __launch_bounds__(256) k_refine2(int npix){
  const uint4* P0 = (const uint4*)g_c0;
  const uint4* P1 = (const uint4*)g_c1;
  unsigned tb4 = g_topbin[4], tb5 = g_topbin[5], tb6 = g_topbin[6], tb7 = g_topbin[7];
  int n4 = npix >> 2;
  int stride = gridDim.x * blockDim.x;
  for (int i = blockIdx.x * blockDim.x + threadIdx.x; i < n4; i += stride){
    uint4 u0 = P0[i], u1 = P1[i];
    unsigned k0[4] = {ukey(u0.x), ukey(u0.y), ukey(u0.z), ukey(u0.w)};
    unsigned k1[4] = {ukey(u1.x), ukey(u1.y), ukey(u1.z), ukey(u1.w)};
    #pragma unroll
    for (int j = 0; j < 4; j++){
      unsigned t0 = k0[j] >> 20, l0 = k0[j] & 0xFFFFFu;
      unsigned t1 = k1[j] >> 20, l1 = k1[j] & 0xFFFFFu;
      if (t0 == tb4) atomicAdd(&g_big[4][l0], 1u);
      if (t0 == tb5) atomicAdd(&g_big[5][l0], 1u);
      if (t1 == tb6) atomicAdd(&g_big[6][l1], 1u);
      if (t1 == tb7) atomicAdd(&g_big[7][l1], 1u);
    }
  }
}

// ---------------- pass 10: fuse G ----------------
__global__ void __launch_bounds__(SCANT, 1) k_scan4(const float* __restrict__ HERef, const float* __restrict__ maxCRef){
  float v[4];
  for (int q = 0; q < 4; q++)
    v[q] = find_val20(g_big[4 + q], g_rankin[4 + q], g_topbin[4 + q]);
  if (threadIdx.x == 0){
    float fc = g_frac[2];
    float maxC0 = v[0] * (1.0f - fc) + v[1] * fc;
    float maxC1 = v[2] * (1.0f - fc) + v[3] * fc;
    float s0 = maxCRef[0] / maxC0;
    float s1 = maxCRef[1] / maxC1;
    for (int i = 0; i < 3; i++)
      for (int j = 0; j < 3; j++)
        g_G[i * 3 + j] = HERef[i * 2 + 0] * s0 * g_A[j] + HERef[i * 2 + 1] * s1 * g_A[3 + j];
  }
}

// ---------------- pass 11: final output ----------------
__global__ void __launch_bounds__(256) k_final(const float* __restrict__ img, float* __restrict__ out, int npix){
  int n4 = npix >> 2;
  const float4* R  = (const float4*)img;
  const float4* Gp = R + n4;
  const float4* Bp = R + 2 * n4;
  float4* O = (float4*)out;
  float G00=g_G[0],G01=g_G[1],G02=g_G[2];
  float G10=g_G[3],G11=g_G[4],G12=g_G[5];
  float G20=g_G[6],G21=g_G[7],G22=g_G[8];
  int stride = gridDim.x * blockDim.x;
  for (int i = blockIdx.x * blockDim.x + threadIdx.x; i < n4; i += stride){
    float4 r = R[i], g = Gp[i], b = Bp[i];
    float rr[4] = {r.x, r.y, r.z, r.w};
    float gg[4] = {g.x, g.y, g.z, g.w};
    float bb[4] = {b.x, b.y, b.z, b.w};
    float res[12];
    #pragma unroll
    for (int j = 0; j < 4; j++){
      float o0 = odv(rr[j]), o1 = odv(gg[j]), o2 = odv(bb[j]);
      float y0 = o0*G00 + o1*G01 + o2*G02;
      float y1 = o0*G10 + o1*G11 + o2*G12;
      float y2 = o0*G20 + o1*G21 + o2*G22;
      res[3*j+0] = floorf(fminf(240.0f * expf(-y0), 255.0f)) / 255.0f;
      res[3*j+1] = floorf(fminf(240.0f * expf(-y1), 255.0f)) / 255.0f;
      res[3*j+2] = floorf(fminf(240.0f * expf(-y2), 255.0f)) / 255.0f;
    }
    O[3*i+0] = make_float4(res[0], res[1], res[2],  res[3]);
    O[3*i+1] = make_float4(res[4], res[5], res[6],  res[7]);
    O[3*i+2] = make_float4(res[8], res[9], res[10], res[11]);
  }
}

// ---------------- launch ----------------
extern "C" void kernel_launch(void* const* d_in, const int* in_sizes, int n_in,
                              void* d_out, int out_size) {
  const float* img     = (const float*)d_in[0];
  const float* HERef   = (const float*)d_in[1];
  const float* maxCRef = (const float*)d_in[2];
  float* out = (float*)d_out;
  int npix = in_sizes[0] / 3;

  k_zero   <<<512, 256>>>();
  k_stats  <<<1024, 256>>>(img, npix);
  k_eig    <<<1, 32>>>();
  k_phi    <<<512, 256>>>(img, npix);
  k_scan1  <<<1, SCANT>>>();
  k_refine1<<<1024, 256>>>(npix);
  k_scan2  <<<1, SCANT>>>();
  k_C      <<<512, 256>>>(img, npix);
  k_scan3  <<<1, SCANT>>>(npix);
  k_refine2<<<1024, 256>>>(npix);
  k_scan4  <<<1, SCANT>>>(HERef, maxCRef);
  k_final  <<<2048, 256>>>(img, out, npix);
}

// round 9
// speedup vs baseline: 15.5561x; 8.1223x over previous
#include <cuda_runtime.h>
#include <stdint.h>

#define MAXPIX 4194304
#define SCANT 512
#define L1BINS 4096
#define L2BINS (1 << 20)
#define SLICES 64
#define SLICEBINS (L2BINS / SLICES)   // 16384

// ---------------- device scratch ----------------
__device__ double             g_acc[9];
__device__ unsigned long long g_cnt;
__device__ unsigned           g_histP [L1BINS];
__device__ unsigned           g_histC0[L1BINS];
__device__ unsigned           g_histC1[L1BINS];
__device__ unsigned           g_big[8][L2BINS];   // 32 MB L2-refine histograms
__device__ unsigned           g_bsum[8][SLICES];  // per-slice sums
__device__ unsigned           g_phi[MAXPIX];      // radix keys
__device__ unsigned           g_c0[MAXPIX];
__device__ unsigned           g_c1[MAXPIX];
__device__ float              g_E[6];        // e_mid(0..2), e_lg(3..5)
__device__ float              g_A[6];        // (HE^T HE)^-1 HE^T   (2x3)
__device__ float              g_G[9];        // fused 3x3
__device__ unsigned           g_topbin[8];
__device__ unsigned           g_rankin[8];
__device__ float              g_frac[3];

// ---------------- helpers ----------------
__device__ __forceinline__ unsigned fkey(float x){
  unsigned u = __float_as_uint(x);
  return (u & 0x80000000u) ? ~u : (u | 0x80000000u);
}
__device__ __forceinline__ float keyf(unsigned k){
  return __uint_as_float((k & 0x80000000u) ? (k ^ 0x80000000u) : ~k);
}
__device__ __forceinline__ float odv(float p){
  return -__logf((floorf(p * 255.0f) + 1.0f) * (1.0f / 240.0f));
}

// ---------------- zero ----------------
__global__ void __launch_bounds__(256, 1) k_zero(){
  int tid = blockIdx.x * blockDim.x + threadIdx.x;
  int stride = gridDim.x * blockDim.x;
  uint4 z = make_uint4(0, 0, 0, 0);
  uint4* B = (uint4*)&g_big[0][0];
  int tot4 = (8 * L2BINS) / 4;
  for (int i = tid; i < tot4; i += stride) B[i] = z;
  if (tid < L1BINS){
    g_histP[tid] = 0u; g_histC0[tid] = 0u; g_histC1[tid] = 0u;
  }
  if (tid == 0){
    g_cnt = 0ull;
    for (int k = 0; k < 9; k++) g_acc[k] = 0.0;
  }
}

// ---------------- pass 1: masked stats (f32 per-thread, f64 reduce) ----------------
__global__ void __launch_bounds__(256) k_stats(const float* __restrict__ img, int npix){
  int n4 = npix >> 2;
  const float4* R  = (const float4*)img;
  const float4* Gp = R + n4;
  const float4* Bp = R + 2 * n4;
  float a[9] = {0,0,0,0,0,0,0,0,0};
  unsigned cnt = 0;
  int stride = gridDim.x * blockDim.x;
  for (int i = blockIdx.x * blockDim.x + threadIdx.x; i < n4; i += stride){
    float4 r = R[i], g = Gp[i], b = Bp[i];
    float rr[4] = {r.x, r.y, r.z, r.w};
    float gg[4] = {g.x, g.y, g.z, g.w};
    float bb[4] = {b.x, b.y, b.z, b.w};
    #pragma unroll
    for (int j = 0; j < 4; j++){
      float o0 = odv(rr[j]), o1 = odv(gg[j]), o2 = odv(bb[j]);
      if (o0 >= 0.15f && o1 >= 0.15f && o2 >= 0.15f){
        a[0] += o0; a[1] += o1; a[2] += o2;
        a[3] += o0*o0; a[4] += o0*o1; a[5] += o0*o2;
        a[6] += o1*o1; a[7] += o1*o2; a[8] += o2*o2;
        cnt++;
      }
    }
  }
  double d[9];
  #pragma unroll
  for (int k = 0; k < 9; k++) d[k] = (double)a[k];
  double c = (double)cnt;
  #pragma unroll
  for (int o = 16; o > 0; o >>= 1){
    #pragma unroll
    for (int k = 0; k < 9; k++) d[k] += __shfl_down_sync(0xffffffffu, d[k], o);
    c += __shfl_down_sync(0xffffffffu, c, o);
  }
  __shared__ double s_acc[10][8];
  int w = threadIdx.x >> 5, lane = threadIdx.x & 31;
  if (lane == 0){
    #pragma unroll
    for (int k = 0; k < 9; k++) s_acc[k][w] = d[k];
    s_acc[9][w] = c;
  }
  __syncthreads();
  if (threadIdx.x == 0){
    int nw = blockDim.x >> 5;
    double t[10] = {0,0,0,0,0,0,0,0,0,0};
    for (int ww = 0; ww < nw; ww++)
      for (int k = 0; k < 10; k++) t[k] += s_acc[k][ww];
    for (int k = 0; k < 9; k++) atomicAdd(&g_acc[k], t[k]);
    atomicAdd(&g_cnt, (unsigned long long)(t[9] + 0.5));
  }
}

// ---------------- pass 2: 3x3 eigh (double Jacobi, 1 thread) ----------------
__global__ void __launch_bounds__(32, 1) k_eig(){
  if (threadIdx.x != 0 || blockIdx.x != 0) return;
  double n = (double)g_cnt;
  double s0 = g_acc[0], s1 = g_acc[1], s2 = g_acc[2];
  double inv = 1.0 / (n - 1.0);
  double a[3][3];
  a[0][0] = (g_acc[3] - s0*s0/n) * inv;
  a[0][1] = a[1][0] = (g_acc[4] - s0*s1/n) * inv;
  a[0][2] = a[2][0] = (g_acc[5] - s0*s2/n) * inv;
  a[1][1] = (g_acc[6] - s1*s1/n) * inv;
  a[1][2] = a[2][1] = (g_acc[7] - s1*s2/n) * inv;
  a[2][2] = (g_acc[8] - s2*s2/n) * inv;
  double V[3][3] = {{1,0,0},{0,1,0},{0,0,1}};
  for (int sweep = 0; sweep < 30; sweep++){
    double off = fabs(a[0][1]) + fabs(a[0][2]) + fabs(a[1][2]);
    if (off < 1e-280) break;
    for (int p = 0; p < 2; p++){
      for (int q = p + 1; q < 3; q++){
        double apq = a[p][q];
        if (fabs(apq) < 1e-300) continue;
        double theta = (a[q][q] - a[p][p]) / (2.0 * apq);
        double t = (theta >= 0.0 ? 1.0 : -1.0) / (fabs(theta) + sqrt(theta*theta + 1.0));
        double c = 1.0 / sqrt(t*t + 1.0);
        double s = t * c;
        double app = a[p][p], aqq = a[q][q];
        a[p][p] = app - t * apq;
        a[q][q] = aqq + t * apq;
        a[p][q] = a[q][p] = 0.0;
        int r = 3 - p - q;
        double arp = a[r][p], arq = a[r][q];
        a[r][p] = a[p][r] = c*arp - s*arq;
        a[r][q] = a[q][r] = s*arp + c*arq;
        for (int k = 0; k < 3; k++){
          double vkp = V[k][p], vkq = V[k][q];
          V[k][p] = c*vkp - s*vkq;
          V[k][q] = s*vkp + c*vkq;
        }
      }
    }
  }
  double w[3] = {a[0][0], a[1][1], a[2][2]};
  int idx[3] = {0,1,2};
  for (int i = 0; i < 2; i++)
    for (int j = i + 1; j < 3; j++)
      if (w[idx[j]] < w[idx[i]]){ int tmp = idx[i]; idx[i] = idx[j]; idx[j] = tmp; }
  int cols[2] = {idx[1], idx[2]};   // middle, largest eigenvalue
  for (int j = 0; j < 2; j++){
    double v0 = V[0][cols[j]], v1 = V[1][cols[j]], v2 = V[2][cols[j]];
    double mx = v0, mxa = fabs(v0);
    if (fabs(v1) > mxa){ mxa = fabs(v1); mx = v1; }
    if (fabs(v2) > mxa){ mxa = fabs(v2); mx = v2; }
    double sgn = (mx < 0.0) ? -1.0 : 1.0;
    g_E[3*j+0] = (float)(v0 * sgn);
    g_E[3*j+1] = (float)(v1 * sgn);
    g_E[3*j+2] = (float)(v2 * sgn);
  }
}

// ---------------- pass 3: phi keys + 12-bit smem histogram ----------------
__global__ void __launch_bounds__(256) k_phi(const float* __restrict__ img, int npix){
  __shared__ unsigned sh[L1BINS];
  for (int b = threadIdx.x; b < L1BINS; b += 256) sh[b] = 0u;
  __syncthreads();
  int n4 = npix >> 2;
  const float4* R  = (const float4*)img;
  const float4* Gp = R + n4;
  const float4* Bp = R + 2 * n4;
  uint4* PH = (uint4*)g_phi;
  float e0=g_E[0],e1=g_E[1],e2=g_E[2],e3=g_E[3],e4=g_E[4],e5=g_E[5];
  int stride = gridDim.x * blockDim.x;
  for (int i = blockIdx.x * blockDim.x + threadIdx.x; i < n4; i += stride){
    float4 r = R[i], g = Gp[i], b = Bp[i];
    float rr[4] = {r.x, r.y, r.z, r.w};
    float gg[4] = {g.x, g.y, g.z, g.w};
    float bb[4] = {b.x, b.y, b.z, b.w};
    unsigned ph[4];
    #pragma unroll
    for (int j = 0; j < 4; j++){
      float o0 = odv(rr[j]), o1 = odv(gg[j]), o2 = odv(bb[j]);
      if (o0 >= 0.15f && o1 >= 0.15f && o2 >= 0.15f){
        float t0 = o0*e0 + o1*e1 + o2*e2;
        float t1 = o0*e3 + o1*e4 + o2*e5;
        unsigned k = fkey(atan2f(t1, t0));
        ph[j] = k;
        atomicAdd(&sh[k >> 20], 1u);
      } else {
        ph[j] = 0xFF800000u;   // key(+inf): sorts last, never histogrammed
      }
    }
    PH[i] = make_uint4(ph[0], ph[1], ph[2], ph[3]);
  }
  __syncthreads();
  for (int b = threadIdx.x; b < L1BINS; b += 256){
    unsigned v = sh[b];
    if (v) atomicAdd(&g_histP[b], v);
  }
}

// ---------------- block scan infra (blockDim == SCANT) ----------------
__device__ unsigned blk_exscan(unsigned v){
  __shared__ unsigned ws[32];
  unsigned lane = threadIdx.x & 31, w = threadIdx.x >> 5;
  unsigned x = v;
  #pragma unroll
  for (int o = 1; o < 32; o <<= 1){
    unsigned y = __shfl_up_sync(0xffffffffu, x, o);
    if (lane >= o) x += y;
  }
  if (lane == 31) ws[w] = x;
  __syncthreads();
  if (threadIdx.x < 32){
    unsigned t = (lane < (SCANT / 32)) ? ws[lane] : 0u;
    #pragma unroll
    for (int o = 1; o < 32; o <<= 1){
      unsigned y = __shfl_up_sync(0xffffffffu, t, o);
      if (lane >= o) t += y;
    }
    ws[lane] = t;
  }
  __syncthreads();
  unsigned base = (w == 0) ? 0u : ws[w - 1];
  unsigned res = base + x - v;
  __syncthreads();
  return res;
}

// find multiple k-th over a 4096-bin L1 histogram (one read pass)
__device__ void find_kth_l1(const unsigned* __restrict__ hist, const unsigned* ranks, int nr,
                            unsigned* out_bin, unsigned* out_rib){
  unsigned base = threadIdx.x * (L1BINS / SCANT);   // 8 bins/thread
  unsigned h[L1BINS / SCANT];
  unsigned s = 0;
  #pragma unroll
  for (int b = 0; b < L1BINS / SCANT; b++){ h[b] = hist[base + b]; s += h[b]; }
  unsigned cum = blk_exscan(s);
  for (int q = 0; q < nr; q++){
    unsigned rank = ranks[q];
    if (rank >= cum && rank < cum + s){
      unsigned c2 = cum;
      #pragma unroll
      for (int b = 0; b < L1BINS / SCANT; b++){
        if (rank < c2 + h[b]){ out_bin[q] = base + b; out_rib[q] = rank - c2; break; }
        c2 += h[b];
      }
    }
  }
  __syncthreads();
}

// ---------------- per-slice partial sums over g_big (full-chip) ----------------
__global__ void __launch_bounds__(256, 1) k_psum(int hbase){
  int hist = hbase + (int)(blockIdx.x / SLICES);
  int slice = blockIdx.x % SLICES;
  const uint4* H = (const uint4*)(&g_big[hist][slice * SLICEBINS]);
  unsigned s = 0;
  for (int i = threadIdx.x; i < SLICEBINS / 4; i += 256){
    uint4 u = H[i];
    s += u.x + u.y + u.z + u.w;
  }
  #pragma unroll
  for (int o = 16; o > 0; o >>= 1) s += __shfl_down_sync(0xffffffffu, s, o);
  __shared__ unsigned sw[8];
  if ((threadIdx.x & 31) == 0) sw[threadIdx.x >> 5] = s;
  __syncthreads();
  if (threadIdx.x == 0){
    unsigned t = 0;
    for (int ww = 0; ww < 8; ww++) t += sw[ww];
    g_bsum[hist][slice] = t;
  }
}

// resolve exact value: pick slice via bsum, then scan one 16K-bin slice
__device__ float resolve20(const unsigned* __restrict__ hist, const unsigned* __restrict__ bsum,
                           unsigned rank, unsigned topbin){
  __shared__ unsigned s_slice, s_rib;
  __shared__ float s_val;
  if (threadIdx.x == 0){
    unsigned cum = 0;
    for (int s = 0; s < SLICES; s++){
      unsigned v = bsum[s];
      if (rank < cum + v){ s_slice = (unsigned)s; s_rib = rank - cum; break; }
      cum += v;
    }
  }
  __syncthreads();
  unsigned slice = s_slice, r = s_rib;
  const uint4* H = (const uint4*)(hist + slice * SLICEBINS);
  const int per = (SLICEBINS / SCANT) / 4;   // 8 uint4 per thread
  unsigned base4 = threadIdx.x * per;
  uint4 u[per];
  unsigned s = 0;
  #pragma unroll
  for (int b = 0; b < per; b++){ u[b] = H[base4 + b]; s += u[b].x + u[b].y + u[b].z + u[b].w; }
  unsigned cum = blk_exscan(s);
  if (r >= cum && r < cum + s){
    unsigned c2 = cum;
    #pragma unroll
    for (int b = 0; b < per; b++){
      unsigned bin = slice * SLICEBINS + (base4 + b) * 4;
      if (r < c2 + u[b].x){ s_val = keyf((topbin << 20) | (bin + 0)); break; } c2 += u[b].x;
      if (r < c2 + u[b].y){ s_val = keyf((topbin << 20) | (bin + 1)); break; } c2 += u[b].y;
      if (r < c2 + u[b].z){ s_val = keyf((topbin << 20) | (bin + 2)); break; } c2 += u[b].z;
      if (r < c2 + u[b].w){ s_val = keyf((topbin << 20) | (bin + 3)); break; } c2 += u[b].w;
    }
  }
  __syncthreads();
  float v = s_val;
  __syncthreads();
  return v;
}

// ---------------- pass 4: phi quantile top bins ----------------
__global__ void __launch_bounds__(SCANT, 1) k_scan1(){
  __shared__ unsigned sh_rank[4];
  if (threadIdx.x == 0){
    unsigned n = (unsigned)g_cnt;
    float nm1 = (float)(n - 1u);
    float p0 = 0.01f * nm1, p1 = 0.99f * nm1;
    float l0 = floorf(p0), l1 = floorf(p1);
    sh_rank[0] = (unsigned)l0; sh_rank[1] = (unsigned)ceilf(p0);
    sh_rank[2] = (unsigned)l1; sh_rank[3] = (unsigned)ceilf(p1);
    g_frac[0] = p0 - l0; g_frac[1] = p1 - l1;
  }
  __syncthreads();
  find_kth_l1(g_histP, sh_rank, 4, &g_topbin[0], &g_rankin[0]);
}

// ---------------- pass 5: phi refine (20-bit) ----------------
__global__ void __launch_bounds__(256) k_refine1(int npix){
  const uint4* P = (const uint4*)g_phi;
  unsigned tb0 = g_topbin[0], tb1 = g_topbin[1], tb2 = g_topbin[2], tb3 = g_topbin[3];
  int n4 = npix >> 2;
  int stride = gridDim.x * blockDim.x;
  for (int i = blockIdx.x * blockDim.x + threadIdx.x; i < n4; i += stride){
    uint4 u = P[i];
    unsigned kk[4] = {u.x, u.y, u.z, u.w};
    #pragma unroll
    for (int j = 0; j < 4; j++){
      unsigned top = kk[j] >> 20, low = kk[j] & 0xFFFFFu;
      if (top == tb0) atomicAdd(&g_big[0][low], 1u);
      if (top == tb1) atomicAdd(&g_big[1][low], 1u);
      if (top == tb2) atomicAdd(&g_big[2][low], 1u);
      if (top == tb3) atomicAdd(&g_big[3][low], 1u);
    }
  }
}

// ---------------- pass 6: HE + solve matrix ----------------
__global__ void __launch_bounds__(SCANT, 1) k_scan2(){
  float v[4];
  for (int q = 0; q < 4; q++)
    v[q] = resolve20(g_big[q], g_bsum[q], g_rankin[q], g_topbin[q]);
  if (threadIdx.x == 0){
    float f0 = g_frac[0], f1 = g_frac[1];
    float minPhi = v[0] * (1.0f - f0) + v[1] * f0;
    float maxPhi = v[2] * (1.0f - f1) + v[3] * f1;
    float cmn = cosf(minPhi), smn = sinf(minPhi);
    float cmx = cosf(maxPhi), smx = sinf(maxPhi);
    float vMin[3], vMax[3];
    for (int i = 0; i < 3; i++){
      vMin[i] = g_E[i] * cmn + g_E[3 + i] * smn;
      vMax[i] = g_E[i] * cmx + g_E[3 + i] * smx;
    }
    float he[3][2];
    if (vMin[0] > vMax[0])
      for (int i = 0; i < 3; i++){ he[i][0] = vMin[i]; he[i][1] = vMax[i]; }
    else
      for (int i = 0; i < 3; i++){ he[i][0] = vMax[i]; he[i][1] = vMin[i]; }
    double m00 = 0, m01 = 0, m11 = 0;
    for (int i = 0; i < 3; i++){
      m00 += (double)he[i][0] * he[i][0];
      m01 += (double)he[i][0] * he[i][1];
      m11 += (double)he[i][1] * he[i][1];
    }
    double det = m00 * m11 - m01 * m01;
    double i00 = m11 / det, i01 = -m01 / det, i11 = m00 / det;
    for (int j = 0; j < 3; j++){
      g_A[j]     = (float)(i00 * he[j][0] + i01 * he[j][1]);
      g_A[3 + j] = (float)(i01 * he[j][0] + i11 * he[j][1]);
    }
  }
}

// ---------------- pass 7: C keys + 12-bit smem histograms ----------------
__global__ void __launch_bounds__(256) k_C(const float* __restrict__ img, int npix){
  __shared__ unsigned sh0[L1BINS];
  __shared__ unsigned sh1[L1BINS];
  for (int b = threadIdx.x; b < L1BINS; b += 256){ sh0[b] = 0u; sh1[b] = 0u; }
  __syncthreads();
  int n4 = npix >> 2;
  const float4* R  = (const float4*)img;
  const float4* Gp = R + n4;
  const float4* Bp = R + 2 * n4;
  uint4* C0 = (uint4*)g_c0;
  uint4* C1 = (uint4*)g_c1;
  float a0=g_A[0],a1=g_A[1],a2=g_A[2],a3=g_A[3],a4=g_A[4],a5=g_A[5];
  int stride = gridDim.x * blockDim.x;
  for (int i = blockIdx.x * blockDim.x + threadIdx.x; i < n4; i += stride){
    float4 r = R[i], g = Gp[i], b = Bp[i];
    float rr[4] = {r.x, r.y, r.z, r.w};
    float gg[4] = {g.x, g.y, g.z, g.w};
    float bb[4] = {b.x, b.y, b.z, b.w};
    unsigned c0v[4], c1v[4];
    #pragma unroll
    for (int j = 0; j < 4; j++){
      float o0 = odv(rr[j]), o1 = odv(gg[j]), o2 = odv(bb[j]);
      unsigned k0 = fkey(o0*a0 + o1*a1 + o2*a2);
      unsigned k1 = fkey(o0*a3 + o1*a4 + o2*a5);
      c0v[j] = k0; c1v[j] = k1;
      atomicAdd(&sh0[k0 >> 20], 1u);
      atomicAdd(&sh1[k1 >> 20], 1u);
    }
    C0[i] = make_uint4(c0v[0], c0v[1], c0v[2], c0v[3]);
    C1[i] = make_uint4(c1v[0], c1v[1], c1v[2], c1v[3]);
  }
  __syncthreads();
  for (int b = threadIdx.x; b < L1BINS; b += 256){
    unsigned v0 = sh0[b]; if (v0) atomicAdd(&g_histC0[b], v0);
    unsigned v1 = sh1[b]; if (v1) atomicAdd(&g_histC1[b], v1);
  }
}

// ---------------- pass 8: C quantile top bins ----------------
__global__ void __launch_bounds__(SCANT, 1) k_scan3(int npix){
  __shared__ unsigned sh_rank[2];
  if (threadIdx.x == 0){
    float nm1 = (float)(npix - 1);
    float p = 0.99f * nm1;
    float l = floorf(p);
    sh_rank[0] = (unsigned)l;
    sh_rank[1] = (unsigned)ceilf(p);
    g_frac[2] = p - l;
  }
  __syncthreads();
  find_kth_l1(g_histC0, sh_rank, 2, &g_topbin[4], &g_rankin[4]);
  find_kth_l1(g_histC1, sh_rank, 2, &g_topbin[6], &g_rankin[6]);
}

// ---------------- pass 9: C refine (20-bit) ----------------
__global__ void __launch_bounds__(256) k_refine2(int npix){
  const uint4* P0 = (const uint4*)g_c0;
  const uint4* P1 = (const uint4*)g_c1;
  unsigned tb4 = g_topbin[4], tb5 = g_topbin[5], tb6 = g_topbin[6], tb7 = g_topbin[7];
  int n4 = npix >> 2;
  int stride = gridDim.x * blockDim.x;
  for (int i = blockIdx.x * blockDim.x + threadIdx.x; i < n4; i += stride){
    uint4 u0 = P0[i], u1 = P1[i];
    unsigned k0[4] = {u0.x, u0.y, u0.z, u0.w};
    unsigned k1[4] = {u1.x, u1.y, u1.z, u1.w};
    #pragma unroll
    for (int j = 0; j < 4; j++){
      unsigned t0 = k0[j] >> 20, l0 = k0[j] & 0xFFFFFu;
      unsigned t1 = k1[j] >> 20, l1 = k1[j] & 0xFFFFFu;
      if (t0 == tb4) atomicAdd(&g_big[4][l0], 1u);
      if (t0 == tb5) atomicAdd(&g_big[5][l0], 1u);
      if (t1 == tb6) atomicAdd(&g_big[6][l1], 1u);
      if (t1 == tb7) atomicAdd(&g_big[7][l1], 1u);
    }
  }
}

// ---------------- pass 10: fuse G ----------------
__global__ void __launch_bounds__(SCANT, 1) k_scan4(const float* __restrict__ HERef, const float* __restrict__ maxCRef){
  float v[4];
  for (int q = 0; q < 4; q++)
    v[q] = resolve20(g_big[4 + q], g_bsum[4 + q], g_rankin[4 + q], g_topbin[4 + q]);
  if (threadIdx.x == 0){
    float fc = g_frac[2];
    float maxC0 = v[0] * (1.0f - fc) + v[1] * fc;
    float maxC1 = v[2] * (1.0f - fc) + v[3] * fc;
    float s0 = maxCRef[0] / maxC0;
    float s1 = maxCRef[1] / maxC1;
    for (int i = 0; i < 3; i++)
      for (int j = 0; j < 3; j++)
        g_G[i * 3 + j] = HERef[i * 2 + 0] * s0 * g_A[j] + HERef[i * 2 + 1] * s1 * g_A[3 + j];
  }
}

// ---------------- pass 11: final output ----------------
__global__ void __launch_bounds__(256) k_final(const float* __restrict__ img, float* __restrict__ out, int npix){
  int n4 = npix >> 2;
  const float4* R  = (const float4*)img;
  const float4* Gp = R + n4;
  const float4* Bp = R + 2 * n4;
  float4* O = (float4*)out;
  float G00=g_G[0],G01=g_G[1],G02=g_G[2];
  float G10=g_G[3],G11=g_G[4],G12=g_G[5];
  float G20=g_G[6],G21=g_G[7],G22=g_G[8];
  int stride = gridDim.x * blockDim.x;
  for (int i = blockIdx.x * blockDim.x + threadIdx.x; i < n4; i += stride){
    float4 r = R[i], g = Gp[i], b = Bp[i];
    float rr[4] = {r.x, r.y, r.z, r.w};
    float gg[4] = {g.x, g.y, g.z, g.w};
    float bb[4] = {b.x, b.y, b.z, b.w};
    float res[12];
    #pragma unroll
    for (int j = 0; j < 4; j++){
      float o0 = odv(rr[j]), o1 = odv(gg[j]), o2 = odv(bb[j]);
      float y0 = o0*G00 + o1*G01 + o2*G02;
      float y1 = o0*G10 + o1*G11 + o2*G12;
      float y2 = o0*G20 + o1*G21 + o2*G22;
      res[3*j+0] = floorf(fminf(240.0f * __expf(-y0), 255.0f)) * (1.0f / 255.0f);
      res[3*j+1] = floorf(fminf(240.0f * __expf(-y1), 255.0f)) * (1.0f / 255.0f);
      res[3*j+2] = floorf(fminf(240.0f * __expf(-y2), 255.0f)) * (1.0f / 255.0f);
    }
    O[3*i+0] = make_float4(res[0], res[1], res[2],  res[3]);
    O[3*i+1] = make_float4(res[4], res[5], res[6],  res[7]);
    O[3*i+2] = make_float4(res[8], res[9], res[10], res[11]);
  }
}

// ---------------- launch ----------------
extern "C" void kernel_launch(void* const* d_in, const int* in_sizes, int n_in,
                              void* d_out, int out_size) {
  const float* img     = (const float*)d_in[0];
  const float* HERef   = (const float*)d_in[1];
  const float* maxCRef = (const float*)d_in[2];
  float* out = (float*)d_out;
  int npix = in_sizes[0] / 3;

  k_zero   <<<512, 256>>>();
  k_stats  <<<1024, 256>>>(img, npix);
  k_eig    <<<1, 32>>>();
  k_phi    <<<512, 256>>>(img, npix);
  k_scan1  <<<1, SCANT>>>();
  k_refine1<<<1024, 256>>>(npix);
  k_psum   <<<4 * SLICES, 256>>>(0);
  k_scan2  <<<1, SCANT>>>();
  k_C      <<<512, 256>>>(img, npix);
  k_scan3  <<<1, SCANT>>>(npix);
  k_refine2<<<1024, 256>>>(npix);
  k_psum   <<<4 * SLICES, 256>>>(4);
  k_scan4  <<<1, SCANT>>>(HERef, maxCRef);
  k_final  <<<2048, 256>>>(img, out, npix);
}

// round 10
// speedup vs baseline: 15.9740x; 1.0269x over previous
#include <cuda_runtime.h>
#include <stdint.h>

#define MAXPIX 4194304
#define SCANT 512
#define L1BINS 4096
#define L2BINS (1 << 20)
#define SLICES 64
#define SLICEBINS (L2BINS / SLICES)   // 16384

// ---------------- device scratch ----------------
__device__ double             g_acc[9];
__device__ unsigned long long g_cnt;
__device__ unsigned           g_histP [L1BINS];
__device__ unsigned           g_histC0[L1BINS];
__device__ unsigned           g_histC1[L1BINS];
__device__ unsigned           g_big[8][L2BINS];   // 32 MB L2-refine histograms
__device__ unsigned           g_bsum[8][SLICES];  // per-slice sums
__device__ unsigned           g_pack[MAXPIX];     // packed byte triples
__device__ unsigned           g_phi[MAXPIX];      // phi radix keys
__device__ float              g_E[6];        // e_mid(0..2), e_lg(3..5)
__device__ float              g_A[6];        // (HE^T HE)^-1 HE^T   (2x3)
__device__ float              g_G[9];        // fused 3x3
__device__ unsigned           g_topbin[8];
__device__ unsigned           g_rankin[8];
__device__ float              g_frac[3];

// ---------------- helpers ----------------
__device__ __forceinline__ unsigned fkey(float x){
  unsigned u = __float_as_uint(x);
  return (u & 0x80000000u) ? ~u : (u | 0x80000000u);
}
__device__ __forceinline__ float keyf(unsigned k){
  return __uint_as_float((k & 0x80000000u) ? (k ^ 0x80000000u) : ~k);
}
// build the shared OD lut (blockDim must be >= 256)
#define BUILD_LUT(lut) \
  do { \
    if (threadIdx.x < 256) \
      lut[threadIdx.x] = -__logf((float)(threadIdx.x + 1) * (1.0f / 240.0f)); \
    __syncthreads(); \
  } while (0)

// ---------------- zero ----------------
__global__ void __launch_bounds__(256, 1) k_zero(){
  int tid = blockIdx.x * blockDim.x + threadIdx.x;
  int stride = gridDim.x * blockDim.x;
  uint4 z = make_uint4(0, 0, 0, 0);
  uint4* B = (uint4*)&g_big[0][0];
  int tot4 = (8 * L2BINS) / 4;
  for (int i = tid; i < tot4; i += stride) B[i] = z;
  if (tid < L1BINS){
    g_histP[tid] = 0u; g_histC0[tid] = 0u; g_histC1[tid] = 0u;
  }
  if (tid == 0){
    g_cnt = 0ull;
    for (int k = 0; k < 9; k++) g_acc[k] = 0.0;
  }
}

// ---------------- pass 1: pack bytes + masked stats ----------------
__global__ void __launch_bounds__(256) k_stats(const float* __restrict__ img, int npix){
  __shared__ float lut[256];
  BUILD_LUT(lut);
  int n4 = npix >> 2;
  const float4* R  = (const float4*)img;
  const float4* Gp = R + n4;
  const float4* Bp = R + 2 * n4;
  uint4* PK = (uint4*)g_pack;
  float a[9] = {0,0,0,0,0,0,0,0,0};
  unsigned cnt = 0;
  int stride = gridDim.x * blockDim.x;
  for (int i = blockIdx.x * blockDim.x + threadIdx.x; i < n4; i += stride){
    float4 r = R[i], g = Gp[i], b = Bp[i];
    float rr[4] = {r.x, r.y, r.z, r.w};
    float gg[4] = {g.x, g.y, g.z, g.w};
    float bb[4] = {b.x, b.y, b.z, b.w};
    unsigned pk[4];
    #pragma unroll
    for (int j = 0; j < 4; j++){
      unsigned b0 = (unsigned)(int)(rr[j] * 255.0f);
      unsigned b1 = (unsigned)(int)(gg[j] * 255.0f);
      unsigned b2 = (unsigned)(int)(bb[j] * 255.0f);
      pk[j] = b0 | (b1 << 8) | (b2 << 16);
      float o0 = lut[b0], o1 = lut[b1], o2 = lut[b2];
      if (o0 >= 0.15f && o1 >= 0.15f && o2 >= 0.15f){
        a[0] += o0; a[1] += o1; a[2] += o2;
        a[3] += o0*o0; a[4] += o0*o1; a[5] += o0*o2;
        a[6] += o1*o1; a[7] += o1*o2; a[8] += o2*o2;
        cnt++;
      }
    }
    PK[i] = make_uint4(pk[0], pk[1], pk[2], pk[3]);
  }
  double d[9];
  #pragma unroll
  for (int k = 0; k < 9; k++) d[k] = (double)a[k];
  double c = (double)cnt;
  #pragma unroll
  for (int o = 16; o > 0; o >>= 1){
    #pragma unroll
    for (int k = 0; k < 9; k++) d[k] += __shfl_down_sync(0xffffffffu, d[k], o);
    c += __shfl_down_sync(0xffffffffu, c, o);
  }
  __shared__ double s_acc[10][8];
  int w = threadIdx.x >> 5, lane = threadIdx.x & 31;
  if (lane == 0){
    #pragma unroll
    for (int k = 0; k < 9; k++) s_acc[k][w] = d[k];
    s_acc[9][w] = c;
  }
  __syncthreads();
  if (threadIdx.x == 0){
    int nw = blockDim.x >> 5;
    double t[10] = {0,0,0,0,0,0,0,0,0,0};
    for (int ww = 0; ww < nw; ww++)
      for (int k = 0; k < 10; k++) t[k] += s_acc[k][ww];
    for (int k = 0; k < 9; k++) atomicAdd(&g_acc[k], t[k]);
    atomicAdd(&g_cnt, (unsigned long long)(t[9] + 0.5));
  }
}

// ---------------- pass 2: 3x3 eigh (double Jacobi, 1 thread) ----------------
__global__ void __launch_bounds__(32, 1) k_eig(){
  if (threadIdx.x != 0 || blockIdx.x != 0) return;
  double n = (double)g_cnt;
  double s0 = g_acc[0], s1 = g_acc[1], s2 = g_acc[2];
  double inv = 1.0 / (n - 1.0);
  double a[3][3];
  a[0][0] = (g_acc[3] - s0*s0/n) * inv;
  a[0][1] = a[1][0] = (g_acc[4] - s0*s1/n) * inv;
  a[0][2] = a[2][0] = (g_acc[5] - s0*s2/n) * inv;
  a[1][1] = (g_acc[6] - s1*s1/n) * inv;
  a[1][2] = a[2][1] = (g_acc[7] - s1*s2/n) * inv;
  a[2][2] = (g_acc[8] - s2*s2/n) * inv;
  double V[3][3] = {{1,0,0},{0,1,0},{0,0,1}};
  for (int sweep = 0; sweep < 30; sweep++){
    double off = fabs(a[0][1]) + fabs(a[0][2]) + fabs(a[1][2]);
    if (off < 1e-280) break;
    for (int p = 0; p < 2; p++){
      for (int q = p + 1; q < 3; q++){
        double apq = a[p][q];
        if (fabs(apq) < 1e-300) continue;
        double theta = (a[q][q] - a[p][p]) / (2.0 * apq);
        double t = (theta >= 0.0 ? 1.0 : -1.0) / (fabs(theta) + sqrt(theta*theta + 1.0));
        double c = 1.0 / sqrt(t*t + 1.0);
        double s = t * c;
        double app = a[p][p], aqq = a[q][q];
        a[p][p] = app - t * apq;
        a[q][q] = aqq + t * apq;
        a[p][q] = a[q][p] = 0.0;
        int r = 3 - p - q;
        double arp = a[r][p], arq = a[r][q];
        a[r][p] = a[p][r] = c*arp - s*arq;
        a[r][q] = a[q][r] = s*arp + c*arq;
        for (int k = 0; k < 3; k++){
          double vkp = V[k][p], vkq = V[k][q];
          V[k][p] = c*vkp - s*vkq;
          V[k][q] = s*vkp + c*vkq;
        }
      }
    }
  }
  double w[3] = {a[0][0], a[1][1], a[2][2]};
  int idx[3] = {0,1,2};
  for (int i = 0; i < 2; i++)
    for (int j = i + 1; j < 3; j++)
      if (w[idx[j]] < w[idx[i]]){ int tmp = idx[i]; idx[i] = idx[j]; idx[j] = tmp; }
  int cols[2] = {idx[1], idx[2]};   // middle, largest eigenvalue
  for (int j = 0; j < 2; j++){
    double v0 = V[0][cols[j]], v1 = V[1][cols[j]], v2 = V[2][cols[j]];
    double mx = v0, mxa = fabs(v0);
    if (fabs(v1) > mxa){ mxa = fabs(v1); mx = v1; }
    if (fabs(v2) > mxa){ mxa = fabs(v2); mx = v2; }
    double sgn = (mx < 0.0) ? -1.0 : 1.0;
    g_E[3*j+0] = (float)(v0 * sgn);
    g_E[3*j+1] = (float)(v1 * sgn);
    g_E[3*j+2] = (float)(v2 * sgn);
  }
}

// ---------------- pass 3: phi keys + 12-bit smem histogram ----------------
__global__ void __launch_bounds__(256) k_phi(int npix){
  __shared__ unsigned sh[L1BINS];
  __shared__ float lut[256];
  BUILD_LUT(lut);
  for (int b = threadIdx.x; b < L1BINS; b += 256) sh[b] = 0u;
  __syncthreads();
  int n4 = npix >> 2;
  const uint4* PK = (const uint4*)g_pack;
  uint4* PH = (uint4*)g_phi;
  float e0=g_E[0],e1=g_E[1],e2=g_E[2],e3=g_E[3],e4=g_E[4],e5=g_E[5];
  int stride = gridDim.x * blockDim.x;
  for (int i = blockIdx.x * blockDim.x + threadIdx.x; i < n4; i += stride){
    uint4 u = PK[i];
    unsigned pk[4] = {u.x, u.y, u.z, u.w};
    unsigned ph[4];
    #pragma unroll
    for (int j = 0; j < 4; j++){
      float o0 = lut[pk[j] & 255u], o1 = lut[(pk[j] >> 8) & 255u], o2 = lut[(pk[j] >> 16) & 255u];
      if (o0 >= 0.15f && o1 >= 0.15f && o2 >= 0.15f){
        float t0 = o0*e0 + o1*e1 + o2*e2;
        float t1 = o0*e3 + o1*e4 + o2*e5;
        unsigned k = fkey(atan2f(t1, t0));
        ph[j] = k;
        atomicAdd(&sh[k >> 20], 1u);
      } else {
        ph[j] = 0xFF800000u;   // key(+inf): sorts last, never histogrammed
      }
    }
    PH[i] = make_uint4(ph[0], ph[1], ph[2], ph[3]);
  }
  __syncthreads();
  for (int b = threadIdx.x; b < L1BINS; b += 256){
    unsigned v = sh[b];
    if (v) atomicAdd(&g_histP[b], v);
  }
}

// ---------------- block scan infra (blockDim == SCANT) ----------------
__device__ unsigned blk_exscan(unsigned v){
  __shared__ unsigned ws[32];
  unsigned lane = threadIdx.x & 31, w = threadIdx.x >> 5;
  unsigned x = v;
  #pragma unroll
  for (int o = 1; o < 32; o <<= 1){
    unsigned y = __shfl_up_sync(0xffffffffu, x, o);
    if (lane >= o) x += y;
  }
  if (lane == 31) ws[w] = x;
  __syncthreads();
  if (threadIdx.x < 32){
    unsigned t = (lane < (SCANT / 32)) ? ws[lane] : 0u;
    #pragma unroll
    for (int o = 1; o < 32; o <<= 1){
      unsigned y = __shfl_up_sync(0xffffffffu, t, o);
      if (lane >= o) t += y;
    }
    ws[lane] = t;
  }
  __syncthreads();
  unsigned base = (w == 0) ? 0u : ws[w - 1];
  unsigned res = base + x - v;
  __syncthreads();
  return res;
}

// find multiple k-th over a 4096-bin L1 histogram (one read pass)
__device__ void find_kth_l1(const unsigned* __restrict__ hist, const unsigned* ranks, int nr,
                            unsigned* out_bin, unsigned* out_rib){
  unsigned base = threadIdx.x * (L1BINS / SCANT);   // 8 bins/thread
  unsigned h[L1BINS / SCANT];
  unsigned s = 0;
  #pragma unroll
  for (int b = 0; b < L1BINS / SCANT; b++){ h[b] = hist[base + b]; s += h[b]; }
  unsigned cum = blk_exscan(s);
  for (int q = 0; q < nr; q++){
    unsigned rank = ranks[q];
    if (rank >= cum && rank < cum + s){
      unsigned c2 = cum;
      #pragma unroll
      for (int b = 0; b < L1BINS / SCANT; b++){
        if (rank < c2 + h[b]){ out_bin[q] = base + b; out_rib[q] = rank - c2; break; }
        c2 += h[b];
      }
    }
  }
  __syncthreads();
}

// ---------------- per-slice partial sums over g_big (full-chip) ----------------
__global__ void __launch_bounds__(256, 1) k_psum(int hbase){
  int hist = hbase + (int)(blockIdx.x / SLICES);
  int slice = blockIdx.x % SLICES;
  const uint4* H = (const uint4*)(&g_big[hist][slice * SLICEBINS]);
  unsigned s = 0;
  for (int i = threadIdx.x; i < SLICEBINS / 4; i += 256){
    uint4 u = H[i];
    s += u.x + u.y + u.z + u.w;
  }
  #pragma unroll
  for (int o = 16; o > 0; o >>= 1) s += __shfl_down_sync(0xffffffffu, s, o);
  __shared__ unsigned sw[8];
  if ((threadIdx.x & 31) == 0) sw[threadIdx.x >> 5] = s;
  __syncthreads();
  if (threadIdx.x == 0){
    unsigned t = 0;
    for (int ww = 0; ww < 8; ww++) t += sw[ww];
    g_bsum[hist][slice] = t;
  }
}

// resolve exact value: pick slice via bsum, then scan one 16K-bin slice
__device__ float resolve20(const unsigned* __restrict__ hist, const unsigned* __restrict__ bsum,
                           unsigned rank, unsigned topbin){
  __shared__ unsigned s_slice, s_rib;
  __shared__ float s_val;
  if (threadIdx.x == 0){
    unsigned cum = 0;
    for (int s = 0; s < SLICES; s++){
      unsigned v = bsum[s];
      if (rank < cum + v){ s_slice = (unsigned)s; s_rib = rank - cum; break; }
      cum += v;
    }
  }
  __syncthreads();
  unsigned slice = s_slice, r = s_rib;
  const uint4* H = (const uint4*)(hist + slice * SLICEBINS);
  const int per = (SLICEBINS / SCANT) / 4;   // 8 uint4 per thread
  unsigned base4 = threadIdx.x * per;
  uint4 u[per];
  unsigned s = 0;
  #pragma unroll
  for (int b = 0; b < per; b++){ u[b] = H[base4 + b]; s += u[b].x + u[b].y + u[b].z + u[b].w; }
  unsigned cum = blk_exscan(s);
  if (r >= cum && r < cum + s){
    unsigned c2 = cum;
    #pragma unroll
    for (int b = 0; b < per; b++){
      unsigned bin = slice * SLICEBINS + (base4 + b) * 4;
      if (r < c2 + u[b].x){ s_val = keyf((topbin << 20) | (bin + 0)); break; } c2 += u[b].x;
      if (r < c2 + u[b].y){ s_val = keyf((topbin << 20) | (bin + 1)); break; } c2 += u[b].y;
      if (r < c2 + u[b].z){ s_val = keyf((topbin << 20) | (bin + 2)); break; } c2 += u[b].z;
      if (r < c2 + u[b].w){ s_val = keyf((topbin << 20) | (bin + 3)); break; } c2 += u[b].w;
    }
  }
  __syncthreads();
  float v = s_val;
  __syncthreads();
  return v;
}

// ---------------- pass 4: phi quantile top bins ----------------
__global__ void __launch_bounds__(SCANT, 1) k_scan1(){
  __shared__ unsigned sh_rank[4];
  if (threadIdx.x == 0){
    unsigned n = (unsigned)g_cnt;
    float nm1 = (float)(n - 1u);
    float p0 = 0.01f * nm1, p1 = 0.99f * nm1;
    float l0 = floorf(p0), l1 = floorf(p1);
    sh_rank[0] = (unsigned)l0; sh_rank[1] = (unsigned)ceilf(p0);
    sh_rank[2] = (unsigned)l1; sh_rank[3] = (unsigned)ceilf(p1);
    g_frac[0] = p0 - l0; g_frac[1] = p1 - l1;
  }
  __syncthreads();
  find_kth_l1(g_histP, sh_rank, 4, &g_topbin[0], &g_rankin[0]);
}

// ---------------- pass 5: phi refine (20-bit) ----------------
__global__ void __launch_bounds__(256) k_refine1(int npix){
  const uint4* P = (const uint4*)g_phi;
  unsigned tb0 = g_topbin[0], tb1 = g_topbin[1], tb2 = g_topbin[2], tb3 = g_topbin[3];
  int n4 = npix >> 2;
  int stride = gridDim.x * blockDim.x;
  for (int i = blockIdx.x * blockDim.x + threadIdx.x; i < n4; i += stride){
    uint4 u = P[i];
    unsigned kk[4] = {u.x, u.y, u.z, u.w};
    #pragma unroll
    for (int j = 0; j < 4; j++){
      unsigned top = kk[j] >> 20, low = kk[j] & 0xFFFFFu;
      if (top == tb0) atomicAdd(&g_big[0][low], 1u);
      if (top == tb1) atomicAdd(&g_big[1][low], 1u);
      if (top == tb2) atomicAdd(&g_big[2][low], 1u);
      if (top == tb3) atomicAdd(&g_big[3][low], 1u);
    }
  }
}

// ---------------- pass 6: HE + solve matrix ----------------
__global__ void __launch_bounds__(SCANT, 1) k_scan2(){
  float v[4];
  for (int q = 0; q < 4; q++)
    v[q] = resolve20(g_big[q], g_bsum[q], g_rankin[q], g_topbin[q]);
  if (threadIdx.x == 0){
    float f0 = g_frac[0], f1 = g_frac[1];
    float minPhi = v[0] * (1.0f - f0) + v[1] * f0;
    float maxPhi = v[2] * (1.0f - f1) + v[3] * f1;
    float cmn = cosf(minPhi), smn = sinf(minPhi);
    float cmx = cosf(maxPhi), smx = sinf(maxPhi);
    float vMin[3], vMax[3];
    for (int i = 0; i < 3; i++){
      vMin[i] = g_E[i] * cmn + g_E[3 + i] * smn;
      vMax[i] = g_E[i] * cmx + g_E[3 + i] * smx;
    }
    float he[3][2];
    if (vMin[0] > vMax[0])
      for (int i = 0; i < 3; i++){ he[i][0] = vMin[i]; he[i][1] = vMax[i]; }
    else
      for (int i = 0; i < 3; i++){ he[i][0] = vMax[i]; he[i][1] = vMin[i]; }
    double m00 = 0, m01 = 0, m11 = 0;
    for (int i = 0; i < 3; i++){
      m00 += (double)he[i][0] * he[i][0];
      m01 += (double)he[i][0] * he[i][1];
      m11 += (double)he[i][1] * he[i][1];
    }
    double det = m00 * m11 - m01 * m01;
    double i00 = m11 / det, i01 = -m01 / det, i11 = m00 / det;
    for (int j = 0; j < 3; j++){
      g_A[j]     = (float)(i00 * he[j][0] + i01 * he[j][1]);
      g_A[3 + j] = (float)(i01 * he[j][0] + i11 * he[j][1]);
    }
  }
}

// shared inline for C keys (identical codegen in k_C and k_refine2)
__device__ __forceinline__ void c_keys(float o0, float o1, float o2,
                                       float a0, float a1, float a2,
                                       float a3, float a4, float a5,
                                       unsigned& k0, unsigned& k1){
  k0 = fkey(o0*a0 + o1*a1 + o2*a2);
  k1 = fkey(o0*a3 + o1*a4 + o2*a5);
}

// ---------------- pass 7: C + 12-bit smem histograms (no key store) ----------------
__global__ void __launch_bounds__(256) k_C(int npix){
  __shared__ unsigned sh0[L1BINS];
  __shared__ unsigned sh1[L1BINS];
  __shared__ float lut[256];
  BUILD_LUT(lut);
  for (int b = threadIdx.x; b < L1BINS; b += 256){ sh0[b] = 0u; sh1[b] = 0u; }
  __syncthreads();
  int n4 = npix >> 2;
  const uint4* PK = (const uint4*)g_pack;
  float a0=g_A[0],a1=g_A[1],a2=g_A[2],a3=g_A[3],a4=g_A[4],a5=g_A[5];
  int stride = gridDim.x * blockDim.x;
  for (int i = blockIdx.x * blockDim.x + threadIdx.x; i < n4; i += stride){
    uint4 u = PK[i];
    unsigned pk[4] = {u.x, u.y, u.z, u.w};
    #pragma unroll
    for (int j = 0; j < 4; j++){
      float o0 = lut[pk[j] & 255u], o1 = lut[(pk[j] >> 8) & 255u], o2 = lut[(pk[j] >> 16) & 255u];
      unsigned k0, k1;
      c_keys(o0, o1, o2, a0, a1, a2, a3, a4, a5, k0, k1);
      atomicAdd(&sh0[k0 >> 20], 1u);
      atomicAdd(&sh1[k1 >> 20], 1u);
    }
  }
  __syncthreads();
  for (int b = threadIdx.x; b < L1BINS; b += 256){
    unsigned v0 = sh0[b]; if (v0) atomicAdd(&g_histC0[b], v0);
    unsigned v1 = sh1[b]; if (v1) atomicAdd(&g_histC1[b], v1);
  }
}

// ---------------- pass 8: C quantile top bins ----------------
__global__ void __launch_bounds__(SCANT, 1) k_scan3(int npix){
  __shared__ unsigned sh_rank[2];
  if (threadIdx.x == 0){
    float nm1 = (float)(npix - 1);
    float p = 0.99f * nm1;
    float l = floorf(p);
    sh_rank[0] = (unsigned)l;
    sh_rank[1] = (unsigned)ceilf(p);
    g_frac[2] = p - l;
  }
  __syncthreads();
  find_kth_l1(g_histC0, sh_rank, 2, &g_topbin[4], &g_rankin[4]);
  find_kth_l1(g_histC1, sh_rank, 2, &g_topbin[6], &g_rankin[6]);
}

// ---------------- pass 9: C refine (recompute keys from pack) ----------------
__global__ void __launch_bounds__(256) k_refine2(int npix){
  __shared__ float lut[256];
  BUILD_LUT(lut);
  const uint4* PK = (const uint4*)g_pack;
  unsigned tb4 = g_topbin[4], tb5 = g_topbin[5], tb6 = g_topbin[6], tb7 = g_topbin[7];
  float a0=g_A[0],a1=g_A[1],a2=g_A[2],a3=g_A[3],a4=g_A[4],a5=g_A[5];
  int n4 = npix >> 2;
  int stride = gridDim.x * blockDim.x;
  for (int i = blockIdx.x * blockDim.x + threadIdx.x; i < n4; i += stride){
    uint4 u = PK[i];
    unsigned pk[4] = {u.x, u.y, u.z, u.w};
    #pragma unroll
    for (int j = 0; j < 4; j++){
      float o0 = lut[pk[j] & 255u], o1 = lut[(pk[j] >> 8) & 255u], o2 = lut[(pk[j] >> 16) & 255u];
      unsigned k0, k1;
      c_keys(o0, o1, o2, a0, a1, a2, a3, a4, a5, k0, k1);
      unsigned t0 = k0 >> 20, l0 = k0 & 0xFFFFFu;
      unsigned t1 = k1 >> 20, l1 = k1 & 0xFFFFFu;
      if (t0 == tb4) atomicAdd(&g_big[4][l0], 1u);
      if (t0 == tb5) atomicAdd(&g_big[5][l0], 1u);
      if (t1 == tb6) atomicAdd(&g_big[6][l1], 1u);
      if (t1 == tb7) atomicAdd(&g_big[7][l1], 1u);
    }
  }
}

// ---------------- pass 10: fuse G ----------------
__global__ void __launch_bounds__(SCANT, 1) k_scan4(const float* __restrict__ HERef, const float* __restrict__ maxCRef){
  float v[4];
  for (int q = 0; q < 4; q++)
    v[q] = resolve20(g_big[4 + q], g_bsum[4 + q], g_rankin[4 + q], g_topbin[4 + q]);
  if (threadIdx.x == 0){
    float fc = g_frac[2];
    float maxC0 = v[0] * (1.0f - fc) + v[1] * fc;
    float maxC1 = v[2] * (1.0f - fc) + v[3] * fc;
    float s0 = maxCRef[0] / maxC0;
    float s1 = maxCRef[1] / maxC1;
    for (int i = 0; i < 3; i++)
      for (int j = 0; j < 3; j++)
        g_G[i * 3 + j] = HERef[i * 2 + 0] * s0 * g_A[j] + HERef[i * 2 + 1] * s1 * g_A[3 + j];
  }
}

// ---------------- pass 11: final output ----------------
__global__ void __launch_bounds__(256) k_final(float* __restrict__ out, int npix){
  __shared__ float lut[256];
  BUILD_LUT(lut);
  int n4 = npix >> 2;
  const uint4* PK = (const uint4*)g_pack;
  float4* O = (float4*)out;
  float G00=g_G[0],G01=g_G[1],G02=g_G[2];
  float G10=g_G[3],G11=g_G[4],G12=g_G[5];
  float G20=g_G[6],G21=g_G[7],G22=g_G[8];
  int stride = gridDim.x * blockDim.x;
  for (int i = blockIdx.x * blockDim.x + threadIdx.x; i < n4; i += stride){
    uint4 u = PK[i];
    unsigned pk[4] = {u.x, u.y, u.z, u.w};
    float res[12];
    #pragma unroll
    for (int j = 0; j < 4; j++){
      float o0 = lut[pk[j] & 255u], o1 = lut[(pk[j] >> 8) & 255u], o2 = lut[(pk[j] >> 16) & 255u];
      float y0 = o0*G00 + o1*G01 + o2*G02;
      float y1 = o0*G10 + o1*G11 + o2*G12;
      float y2 = o0*G20 + o1*G21 + o2*G22;
      res[3*j+0] = floorf(fminf(240.0f * __expf(-y0), 255.0f)) * (1.0f / 255.0f);
      res[3*j+1] = floorf(fminf(240.0f * __expf(-y1), 255.0f)) * (1.0f / 255.0f);
      res[3*j+2] = floorf(fminf(240.0f * __expf(-y2), 255.0f)) * (1.0f / 255.0f);
    }
    O[3*i+0] = make_float4(res[0], res[1], res[2],  res[3]);
    O[3*i+1] = make_float4(res[4], res[5], res[6],  res[7]);
    O[3*i+2] = make_float4(res[8], res[9], res[10], res[11]);
  }
}

// ---------------- launch ----------------
extern "C" void kernel_launch(void* const* d_in, const int* in_sizes, int n_in,
                              void* d_out, int out_size) {
  const float* img     = (const float*)d_in[0];
  const float* HERef   = (const float*)d_in[1];
  const float* maxCRef = (const float*)d_in[2];
  float* out = (float*)d_out;
  int npix = in_sizes[0] / 3;

  k_zero   <<<512, 256>>>();
  k_stats  <<<1024, 256>>>(img, npix);
  k_eig    <<<1, 32>>>();
  k_phi    <<<512, 256>>>(npix);
  k_scan1  <<<1, SCANT>>>();
  k_refine1<<<1024, 256>>>(npix);
  k_psum   <<<4 * SLICES, 256>>>(0);
  k_scan2  <<<1, SCANT>>>();
  k_C      <<<512, 256>>>(npix);
  k_scan3  <<<1, SCANT>>>(npix);
  k_refine2<<<1024, 256>>>(npix);
  k_psum   <<<4 * SLICES, 256>>>(4);
  k_scan4  <<<1, SCANT>>>(HERef, maxCRef);
  k_final  <<<2048, 256>>>(out, npix);
}